// round 1
// baseline (speedup 1.0000x reference)
#include <cuda_runtime.h>
#include <math.h>

// Problem constants
#define B_    4
#define HQ_   32
#define HKV_  8
#define D_    128
#define SPAST 8192
#define KVLEN 8193
#define HID   4096
#define NTOT  6144            // 4096 (q) + 1024 (k) + 1024 (v)
#define TOKB  256
#define INITB 4
#define RECB  256
#define NKEEP (INITB + TOKB + RECB)   // 516
#define NCAND 7933            // positions [4, 7936]
#define SSTRIDE 8208          // padded score row stride
#define SCALE 0.08838834764831845f   // 1/sqrt(128)

// ------------- scratch (no allocations allowed) -------------
__device__ float g_part  [8 * 4 * NTOT];     // qkv split-K partials
__device__ float g_q     [B_ * HQ_ * D_];
__device__ float g_knew  [B_ * HKV_ * D_];
__device__ float g_vnew  [B_ * HKV_ * D_];
__device__ float g_scores[B_ * HQ_ * SSTRIDE];
__device__ int   g_sel   [B_ * HQ_ * TOKB];
__device__ float g_attn  [B_ * HQ_ * D_];
__device__ float g_part2 [8 * 4 * HID];

// ------------- helpers -------------
__device__ __forceinline__ float warpsum(float v) {
    #pragma unroll
    for (int o = 16; o > 0; o >>= 1) v += __shfl_xor_sync(0xFFFFFFFFu, v, o);
    return v;
}
__device__ __forceinline__ float warpmax(float v) {
    #pragma unroll
    for (int o = 16; o > 0; o >>= 1) v = fmaxf(v, __shfl_xor_sync(0xFFFFFFFFu, v, o));
    return v;
}

// ------------- Kernel 1: QKV GEMV (split-K) -------------
// grid (48, 8), block 128. Each block: 128 output cols x 512-K chunk, 4 batches.
__global__ void qkv_gemv(const float* __restrict__ h, const float* __restrict__ wq,
                         const float* __restrict__ wk, const float* __restrict__ wv) {
    __shared__ float sh[2048];  // [4][512]
    int tid = threadIdx.x;
    int k0 = blockIdx.y * 512;
    #pragma unroll
    for (int i = tid; i < 2048; i += 128) {
        int b = i >> 9, k = i & 511;
        sh[i] = h[b * HID + k0 + k];
    }
    __syncthreads();
    int c0 = blockIdx.x * 128;
    const float* w; int stride, col;
    if (c0 < 4096)      { w = wq; stride = 4096; col = c0; }
    else if (c0 < 5120) { w = wk; stride = 1024; col = c0 - 4096; }
    else                { w = wv; stride = 1024; col = c0 - 5120; }
    const float* wp = w + (size_t)k0 * stride + col + tid;
    float a0 = 0.f, a1 = 0.f, a2 = 0.f, a3 = 0.f;
    #pragma unroll 8
    for (int k = 0; k < 512; k++) {
        float x = wp[(size_t)k * stride];
        a0 = fmaf(sh[k], x, a0);
        a1 = fmaf(sh[512 + k], x, a1);
        a2 = fmaf(sh[1024 + k], x, a2);
        a3 = fmaf(sh[1536 + k], x, a3);
    }
    int c = c0 + tid;
    float* gp = g_part + (size_t)blockIdx.y * (4 * NTOT);
    gp[c] = a0; gp[NTOT + c] = a1; gp[2 * NTOT + c] = a2; gp[3 * NTOT + c] = a3;
}

// ------------- Kernel 2: reduce partials + RoPE -------------
__global__ void qkv_reduce(const float* __restrict__ cosp, const float* __restrict__ sinp) {
    int idx = blockIdx.x * blockDim.x + threadIdx.x;
    if (idx >= 4 * NTOT) return;
    int b = idx / NTOT, col = idx % NTOT;
    float s = 0.f;
    #pragma unroll
    for (int ks = 0; ks < 8; ks++) s += g_part[(ks * 4 + b) * NTOT + col];
    if (col < 5120) {
        // q (cols 0..4095) or k_new (cols 4096..5119): apply RoPE
        int base = (col < 4096) ? 0 : 4096;
        int lc = col - base;
        int head = lc >> 7, d = lc & 127;
        int pd = (d < 64) ? d + 64 : d - 64;
        int pcol = base + head * 128 + pd;
        float ps = 0.f;
        #pragma unroll
        for (int ks = 0; ks < 8; ks++) ps += g_part[(ks * 4 + b) * NTOT + pcol];
        float c = cosp[b * D_ + d], sn = sinp[b * D_ + d];
        float r = fmaf(s, c, ((d < 64) ? -ps : ps) * sn);
        if (col < 4096) g_q[(b * HQ_ + head) * D_ + d] = r;
        else            g_knew[(b * HKV_ + head) * D_ + d] = r;
    } else {
        int lc = col - 5120;
        g_vnew[b * HKV_ * D_ + lc] = s;
    }
}

// ------------- Kernel 3: scores for all 8193 positions -------------
// grid (33, 32): blockIdx.y = b*8+hkv, chunk of 256 positions. 256 threads.
// Warp per K row: 32 lanes x float4 = 128 floats. 4 q-heads share each K read.
__global__ void scores_kernel(const float* __restrict__ pk) {
    int bh = blockIdx.y;
    int b = bh >> 3, hkv = bh & 7;
    int tid = threadIdx.x, warp = tid >> 5, lane = tid & 31;
    __shared__ float qsh[512];
    const float* qsrc = g_q + (size_t)(b * HQ_ + hkv * 4) * D_;  // 4 contiguous heads
    for (int i = tid; i < 512; i += 256) qsh[i] = qsrc[i];
    __syncthreads();
    float4 q0 = *(const float4*)(qsh +   0 + lane * 4);
    float4 q1 = *(const float4*)(qsh + 128 + lane * 4);
    float4 q2 = *(const float4*)(qsh + 256 + lane * 4);
    float4 q3 = *(const float4*)(qsh + 384 + lane * 4);
    int base = blockIdx.x * 256;
    int end = min(base + 256, KVLEN);
    float* srow = g_scores + (size_t)(b * HQ_ + hkv * 4) * SSTRIDE;
    const float* kbase = pk + ((size_t)bh << 20);  // *8192*128
    for (int p = base + warp; p < end; p += 8) {
        const float* kr = (p < SPAST) ? (kbase + ((size_t)p << 7)) : (g_knew + bh * D_);
        float4 kv = *(const float4*)(kr + lane * 4);
        float d0 = kv.x * q0.x + kv.y * q0.y + kv.z * q0.z + kv.w * q0.w;
        float d1 = kv.x * q1.x + kv.y * q1.y + kv.z * q1.z + kv.w * q1.w;
        float d2 = kv.x * q2.x + kv.y * q2.y + kv.z * q2.z + kv.w * q2.w;
        float d3 = kv.x * q3.x + kv.y * q3.y + kv.z * q3.z + kv.w * q3.w;
        d0 = warpsum(d0); d1 = warpsum(d1); d2 = warpsum(d2); d3 = warpsum(d3);
        if (lane == 0) {
            srow[p]               = d0 * SCALE;
            srow[SSTRIDE + p]     = d1 * SCALE;
            srow[2 * SSTRIDE + p] = d2 * SCALE;
            srow[3 * SSTRIDE + p] = d3 * SCALE;
        }
    }
}

// ------------- Kernel 4: exact radix select of top-256 threshold + index list -------------
// One block per (b, hq). 256 threads. Candidates: pos in [4, 7936] (7933).
__global__ void select_kernel() {
    int bh = blockIdx.x;
    int tid = threadIdx.x;
    __shared__ unsigned keys[NCAND];
    __shared__ int hist[256];
    __shared__ unsigned sh_prefix;
    __shared__ int sh_kk, sh_cntgt, sh_wpos, sh_eqcnt;

    const float* srow = g_scores + (size_t)bh * SSTRIDE;
    for (int i = tid; i < NCAND; i += 256) {
        unsigned u = __float_as_uint(srow[INITB + i]);
        // order-preserving float->uint transform
        u = (u & 0x80000000u) ? ~u : (u | 0x80000000u);
        keys[i] = u;
    }
    if (tid == 0) { sh_prefix = 0; sh_kk = TOKB; sh_cntgt = 0; sh_wpos = 0; sh_eqcnt = 0; }
    __syncthreads();
    unsigned mask = 0;
    for (int shift = 24; shift >= 0; shift -= 8) {
        if (tid < 256) hist[tid] = 0;
        __syncthreads();
        unsigned pfx = sh_prefix;
        for (int i = tid; i < NCAND; i += 256) {
            unsigned u = keys[i];
            if ((u & mask) == pfx) atomicAdd(&hist[(u >> shift) & 255], 1);
        }
        __syncthreads();
        if (tid == 0) {
            int kk = sh_kk, cum = 0;
            for (int bin = 255; bin >= 0; bin--) {
                int c = hist[bin];
                if (cum + c >= kk) {
                    sh_prefix = pfx | ((unsigned)bin << shift);
                    sh_kk = kk - cum;
                    break;
                }
                cum += c;
            }
        }
        mask |= (0xFFu << shift);
        __syncthreads();
    }
    unsigned tau = sh_prefix;
    for (int i = tid; i < NCAND; i += 256)
        if (keys[i] > tau) atomicAdd(&sh_cntgt, 1);
    __syncthreads();
    int need_eq = TOKB - sh_cntgt;
    int* sel = g_sel + bh * TOKB;
    for (int i = tid; i < NCAND; i += 256) {
        unsigned u = keys[i];
        if (u > tau) {
            int s = atomicAdd(&sh_wpos, 1);
            sel[s] = INITB + i;
        } else if (u == tau) {
            int e = atomicAdd(&sh_eqcnt, 1);
            if (e < need_eq) {
                int s = atomicAdd(&sh_wpos, 1);
                sel[s] = INITB + i;
            }
        }
    }
}

// ------------- Kernel 5: softmax over 516 kept positions + weighted V gather -------------
// One block per (b, hq). 256 threads = 8 warps. Warp per V row, lane = float4 of D.
__global__ void attnv_kernel(const float* __restrict__ pv) {
    int bh = blockIdx.x;
    int b = bh >> 5, hq = bh & 31, hkv = hq >> 2;
    int tid = threadIdx.x, warp = tid >> 5, lane = tid & 31;
    __shared__ float sc[NKEEP];
    __shared__ int   idx[NKEEP];
    __shared__ float red[8];
    __shared__ float M_sh, Z_sh;
    __shared__ float outsh[8 * 128];
    const float* srow = g_scores + (size_t)bh * SSTRIDE;
    const int* sel = g_sel + bh * TOKB;
    for (int i = tid; i < NKEEP; i += 256) {
        int p;
        if (i < INITB) p = i;
        else if (i < INITB + TOKB) p = sel[i - INITB];
        else p = (KVLEN - RECB) + (i - INITB - TOKB);  // 7937..8192
        idx[i] = p;
        sc[i] = srow[p];
    }
    __syncthreads();
    float m = -INFINITY;
    for (int i = tid; i < NKEEP; i += 256) m = fmaxf(m, sc[i]);
    m = warpmax(m);
    if (lane == 0) red[warp] = m;
    __syncthreads();
    if (tid == 0) {
        float mm = red[0];
        #pragma unroll
        for (int w = 1; w < 8; w++) mm = fmaxf(mm, red[w]);
        M_sh = mm;
    }
    __syncthreads();
    float M = M_sh, z = 0.f;
    for (int i = tid; i < NKEEP; i += 256) {
        float e = expf(sc[i] - M);
        sc[i] = e;
        z += e;
    }
    z = warpsum(z);
    if (lane == 0) red[warp] = z;
    __syncthreads();
    if (tid == 0) {
        float zz = 0.f;
        #pragma unroll
        for (int w = 0; w < 8; w++) zz += red[w];
        Z_sh = zz;
    }
    __syncthreads();
    float inv = 1.0f / Z_sh;
    float4 acc = make_float4(0.f, 0.f, 0.f, 0.f);
    const float* vbase = pv + ((size_t)(b * HKV_ + hkv) << 20);
    for (int i = warp; i < NKEEP; i += 8) {
        int p = idx[i];
        const float* vr = (p < SPAST) ? (vbase + ((size_t)p << 7)) : (g_vnew + (b * HKV_ + hkv) * D_);
        float4 v = *(const float4*)(vr + lane * 4);
        float w = sc[i] * inv;
        acc.x = fmaf(w, v.x, acc.x);
        acc.y = fmaf(w, v.y, acc.y);
        acc.z = fmaf(w, v.z, acc.z);
        acc.w = fmaf(w, v.w, acc.w);
    }
    float* os = outsh + warp * 128 + lane * 4;
    os[0] = acc.x; os[1] = acc.y; os[2] = acc.z; os[3] = acc.w;
    __syncthreads();
    if (tid < 128) {
        float s = 0.f;
        #pragma unroll
        for (int w = 0; w < 8; w++) s += outsh[w * 128 + tid];
        g_attn[bh * D_ + tid] = s;
    }
}

// ------------- Kernel 6: output projection GEMV (split-K) -------------
__global__ void out_gemv(const float* __restrict__ wo) {
    __shared__ float sh[2048];
    int tid = threadIdx.x;
    int k0 = blockIdx.y * 512;
    #pragma unroll
    for (int i = tid; i < 2048; i += 128) {
        int b = i >> 9, k = i & 511;
        sh[i] = g_attn[b * HID + k0 + k];
    }
    __syncthreads();
    int col = blockIdx.x * 128 + tid;
    const float* wp = wo + (size_t)k0 * HID + col;
    float a0 = 0.f, a1 = 0.f, a2 = 0.f, a3 = 0.f;
    #pragma unroll 8
    for (int k = 0; k < 512; k++) {
        float x = wp[(size_t)k * HID];
        a0 = fmaf(sh[k], x, a0);
        a1 = fmaf(sh[512 + k], x, a1);
        a2 = fmaf(sh[1024 + k], x, a2);
        a3 = fmaf(sh[1536 + k], x, a3);
    }
    float* gp = g_part2 + (size_t)blockIdx.y * (4 * HID);
    gp[col] = a0; gp[HID + col] = a1; gp[2 * HID + col] = a2; gp[3 * HID + col] = a3;
}

__global__ void out_reduce(float* __restrict__ out) {
    int idx = blockIdx.x * blockDim.x + threadIdx.x;
    if (idx >= 4 * HID) return;
    int b = idx >> 12, col = idx & 4095;
    float s = 0.f;
    #pragma unroll
    for (int ks = 0; ks < 8; ks++) s += g_part2[ks * (4 * HID) + b * HID + col];
    out[idx] = s;
}

// ------------- launch -------------
extern "C" void kernel_launch(void* const* d_in, const int* in_sizes, int n_in,
                              void* d_out, int out_size) {
    const float* h    = (const float*)d_in[0];  // hidden_states (4,1,4096)
    const float* cosp = (const float*)d_in[1];  // cos (4,1,128)
    const float* sinp = (const float*)d_in[2];  // sin (4,1,128)
    const float* pk   = (const float*)d_in[3];  // past_key (4,8,8192,128)
    const float* pv   = (const float*)d_in[4];  // past_value (4,8,8192,128)
    const float* wq   = (const float*)d_in[5];  // (4096,4096)
    const float* wk   = (const float*)d_in[6];  // (4096,1024)
    const float* wv   = (const float*)d_in[7];  // (4096,1024)
    const float* wo   = (const float*)d_in[8];  // (4096,4096)
    float* out = (float*)d_out;                 // (4,1,4096)

    qkv_gemv<<<dim3(48, 8), 128>>>(h, wq, wk, wv);
    qkv_reduce<<<(4 * NTOT + 255) / 256, 256>>>(cosp, sinp);
    scores_kernel<<<dim3(33, 32), 256>>>(pk);
    select_kernel<<<128, 256>>>();
    attnv_kernel<<<128, 256>>>(pv);
    out_gemv<<<dim3(32, 8), 128>>>(wo);
    out_reduce<<<(4 * HID + 255) / 256, 256>>>(out);
}

// round 2
// speedup vs baseline: 2.3429x; 2.3429x over previous
#include <cuda_runtime.h>
#include <math.h>

// Problem constants
#define B_    4
#define HQ_   32
#define HKV_  8
#define D_    128
#define SPAST 8192
#define KVLEN 8193
#define HID   4096
#define NTOT  6144            // 4096 (q) + 1024 (k) + 1024 (v)
#define TOKB  256
#define INITB 4
#define RECB  256
#define NKEEP (INITB + TOKB + RECB)   // 516
#define NCAND 7933            // positions [4, 7936]
#define SSTRIDE 8208
#define SCALE 0.08838834764831845f
#define NSPLIT 32             // split-K factor (K-chunk = 128)

// ------------- scratch (no allocations allowed) -------------
__device__ float g_part  [NSPLIT * 4 * NTOT];   // 3 MB
__device__ float g_part2 [NSPLIT * 4 * HID];    // 2 MB
__device__ float g_q     [B_ * HQ_ * D_];
__device__ float g_knew  [B_ * HKV_ * D_];
__device__ float g_vnew  [B_ * HKV_ * D_];
__device__ float g_scores[B_ * HQ_ * SSTRIDE];  // 4 MB
__device__ int   g_sel   [B_ * HQ_ * TOKB];
__device__ float g_attn  [B_ * HQ_ * D_];
__device__ unsigned g_aux[B_ * HQ_ * 7936];     // compacted radix candidates

// ------------- helpers -------------
__device__ __forceinline__ float warpsum(float v) {
    #pragma unroll
    for (int o = 16; o > 0; o >>= 1) v += __shfl_xor_sync(0xFFFFFFFFu, v, o);
    return v;
}
__device__ __forceinline__ float warpmax(float v) {
    #pragma unroll
    for (int o = 16; o > 0; o >>= 1) v = fmaxf(v, __shfl_xor_sync(0xFFFFFFFFu, v, o));
    return v;
}
__device__ __forceinline__ float dot4(float4 a, float4 b) {
    return a.x * b.x + a.y * b.y + a.z * b.z + a.w * b.w;
}

// ------------- Kernel 1: QKV GEMV (split-K, float4 weight loads) -------------
// grid (12, NSPLIT), block 128. Block covers 512 output cols x 128-K chunk, 4 batches.
__global__ void qkv_gemv(const float* __restrict__ h, const float* __restrict__ wq,
                         const float* __restrict__ wk, const float* __restrict__ wv) {
    __shared__ float sh[512];  // [4 batches][128 k]
    int tid = threadIdx.x;
    int k0 = blockIdx.y * 128;
    for (int i = tid; i < 512; i += 128) {
        int b = i >> 7, k = i & 127;
        sh[i] = h[b * HID + k0 + k];
    }
    __syncthreads();
    int c0 = blockIdx.x * 512;
    const float* w; int stride, col;
    if (c0 < 4096)      { w = wq; stride = 4096; col = c0; }
    else if (c0 < 5120) { w = wk; stride = 1024; col = c0 - 4096; }
    else                { w = wv; stride = 1024; col = c0 - 5120; }
    const float* wp = w + (size_t)k0 * stride + col + tid * 4;
    float4 a0 = make_float4(0,0,0,0), a1 = a0, a2 = a0, a3 = a0;
    #pragma unroll 8
    for (int k = 0; k < 128; k++) {
        float4 wv4 = *(const float4*)(wp + (size_t)k * stride);
        float h0 = sh[k], h1 = sh[128 + k], h2 = sh[256 + k], h3 = sh[384 + k];
        a0.x = fmaf(h0, wv4.x, a0.x); a0.y = fmaf(h0, wv4.y, a0.y);
        a0.z = fmaf(h0, wv4.z, a0.z); a0.w = fmaf(h0, wv4.w, a0.w);
        a1.x = fmaf(h1, wv4.x, a1.x); a1.y = fmaf(h1, wv4.y, a1.y);
        a1.z = fmaf(h1, wv4.z, a1.z); a1.w = fmaf(h1, wv4.w, a1.w);
        a2.x = fmaf(h2, wv4.x, a2.x); a2.y = fmaf(h2, wv4.y, a2.y);
        a2.z = fmaf(h2, wv4.z, a2.z); a2.w = fmaf(h2, wv4.w, a2.w);
        a3.x = fmaf(h3, wv4.x, a3.x); a3.y = fmaf(h3, wv4.y, a3.y);
        a3.z = fmaf(h3, wv4.z, a3.z); a3.w = fmaf(h3, wv4.w, a3.w);
    }
    int c = c0 + tid * 4;
    float* gp = g_part + (size_t)blockIdx.y * (4 * NTOT);
    *(float4*)(gp + c)            = a0;
    *(float4*)(gp + NTOT + c)     = a1;
    *(float4*)(gp + 2 * NTOT + c) = a2;
    *(float4*)(gp + 3 * NTOT + c) = a3;
}

// ------------- Kernel 2: reduce split-K partials + RoPE -------------
// q/k handled as rotation pairs (d, d+64); v straight sum.
__global__ void qkv_reduce(const float* __restrict__ cosp, const float* __restrict__ sinp) {
    int idx = blockIdx.x * blockDim.x + threadIdx.x;
    if (idx >= 4 * 3584) return;
    int b = idx / 3584, r = idx % 3584;
    if (r < 2560) {
        int head = r >> 6, d = r & 63;
        int col1 = head * 128 + d, col2 = col1 + 64;
        float s1 = 0.f, s2 = 0.f;
        #pragma unroll
        for (int ks = 0; ks < NSPLIT; ks++) {
            const float* gp = g_part + (size_t)(ks * 4 + b) * NTOT;
            s1 += gp[col1]; s2 += gp[col2];
        }
        float c1 = cosp[b * D_ + d],      sn1 = sinp[b * D_ + d];
        float c2 = cosp[b * D_ + d + 64], sn2 = sinp[b * D_ + d + 64];
        float r1 = s1 * c1 - s2 * sn1;
        float r2 = s2 * c2 + s1 * sn2;
        if (head < 32) {
            g_q[(b * HQ_ + head) * D_ + d]      = r1;
            g_q[(b * HQ_ + head) * D_ + d + 64] = r2;
        } else {
            int kh = head - 32;
            g_knew[(b * HKV_ + kh) * D_ + d]      = r1;
            g_knew[(b * HKV_ + kh) * D_ + d + 64] = r2;
        }
    } else {
        int lc = r - 2560;
        float s = 0.f;
        #pragma unroll
        for (int ks = 0; ks < NSPLIT; ks++)
            s += g_part[(size_t)(ks * 4 + b) * NTOT + 5120 + lc];
        g_vnew[b * HKV_ * D_ + lc] = s;
    }
}

// ------------- Kernel 3: scores (warp-per-row, 4-row unroll, 4 q-heads per K read) -------------
// grid (33, 32): blockIdx.y = b*8+hkv, 256-position chunk. 256 threads.
__global__ void scores_kernel(const float* __restrict__ pk) {
    int bh = blockIdx.y;
    int b = bh >> 3, hkv = bh & 7;
    int tid = threadIdx.x, warp = tid >> 5, lane = tid & 31;
    __shared__ float qsh[512];
    const float* qsrc = g_q + (size_t)(b * HQ_ + hkv * 4) * D_;
    for (int i = tid; i < 512; i += 256) qsh[i] = qsrc[i];
    __syncthreads();
    float4 q0 = *(const float4*)(qsh +   0 + lane * 4);
    float4 q1 = *(const float4*)(qsh + 128 + lane * 4);
    float4 q2 = *(const float4*)(qsh + 256 + lane * 4);
    float4 q3 = *(const float4*)(qsh + 384 + lane * 4);
    int base = blockIdx.x * 256;
    float* srow = g_scores + (size_t)(b * HQ_ + hkv * 4) * SSTRIDE;
    const float* kbase = pk + ((size_t)bh << 20);
    const float* knrow = g_knew + bh * D_;
    int p0 = base + warp * 32;
    for (int j = 0; j < 32; j += 4) {
        int p = p0 + j;
        if (p >= KVLEN) break;
        const float* r0p = (p     < SPAST) ? kbase + ((size_t) p      << 7) : knrow;
        const float* r1p = (p + 1 < SPAST) ? kbase + ((size_t)(p + 1) << 7) : knrow;
        const float* r2p = (p + 2 < SPAST) ? kbase + ((size_t)(p + 2) << 7) : knrow;
        const float* r3p = (p + 3 < SPAST) ? kbase + ((size_t)(p + 3) << 7) : knrow;
        float4 k0v = *(const float4*)(r0p + lane * 4);
        float4 k1v = *(const float4*)(r1p + lane * 4);
        float4 k2v = *(const float4*)(r2p + lane * 4);
        float4 k3v = *(const float4*)(r3p + lane * 4);
        float d_[16];
        d_[ 0] = dot4(k0v, q0); d_[ 1] = dot4(k0v, q1); d_[ 2] = dot4(k0v, q2); d_[ 3] = dot4(k0v, q3);
        d_[ 4] = dot4(k1v, q0); d_[ 5] = dot4(k1v, q1); d_[ 6] = dot4(k1v, q2); d_[ 7] = dot4(k1v, q3);
        d_[ 8] = dot4(k2v, q0); d_[ 9] = dot4(k2v, q1); d_[10] = dot4(k2v, q2); d_[11] = dot4(k2v, q3);
        d_[12] = dot4(k3v, q0); d_[13] = dot4(k3v, q1); d_[14] = dot4(k3v, q2); d_[15] = dot4(k3v, q3);
        #pragma unroll
        for (int t = 0; t < 16; t++) d_[t] = warpsum(d_[t]);
        if (lane == 0) {
            if (p + 3 < KVLEN) {
                #pragma unroll
                for (int h = 0; h < 4; h++) {
                    float4 s4 = make_float4(d_[h] * SCALE, d_[4 + h] * SCALE,
                                            d_[8 + h] * SCALE, d_[12 + h] * SCALE);
                    *(float4*)(srow + h * SSTRIDE + p) = s4;
                }
            } else {
                #pragma unroll
                for (int h = 0; h < 4; h++)
                    for (int i = 0; i < 4; i++)
                        if (p + i < KVLEN) srow[h * SSTRIDE + p + i] = d_[i * 4 + h] * SCALE;
            }
        }
    }
}

// ------------- Kernel 4: top-256 exact radix select with compaction -------------
// One block per (b, hq). 512 threads. keys in SMEM, parallel suffix-scan bin pick,
// candidates compacted to g_aux after 2 passes.
__shared__ unsigned s_keys[7936];
__device__ __forceinline__ void scan_pick(int* hist, int* warpsums, int* sh_bin,
                                          int* sh_kk, int tid) {
    int kk = *sh_kk;                     // last write was before a __syncthreads()
    int v = 0, prev = 0;
    if (tid < 256) {
        int bin = 255 - tid;
        v = hist[bin];
        int lane = tid & 31, w = tid >> 5;
        #pragma unroll
        for (int o = 1; o < 32; o <<= 1) {
            int n = __shfl_up_sync(0xFFFFFFFFu, v, o);
            if (lane >= o) v += n;
        }
        if (lane == 31) warpsums[w] = v;
    }
    __syncthreads();
    if (tid == 0) {
        int a = 0;
        #pragma unroll
        for (int w = 0; w < 8; w++) { int t = warpsums[w]; warpsums[w] = a; a += t; }
    }
    __syncthreads();
    if (tid < 256) {
        v += warpsums[tid >> 5];
        prev = v - hist[255 - tid];
        if (v >= kk && prev < kk) { *sh_bin = 255 - tid; *sh_kk = kk - prev; }
    }
    __syncthreads();
}

__global__ void select_kernel() {
    __shared__ unsigned keys[7936];
    __shared__ int hist[256];
    __shared__ int warpsums[8];
    __shared__ int sh_bin, sh_kk, sh_wpos, sh_naux, sh_eq;
    int bh = blockIdx.x, tid = threadIdx.x;
    const float* srow = g_scores + (size_t)bh * SSTRIDE;
    for (int i = tid; i < NCAND; i += 512) {
        unsigned u = __float_as_uint(srow[INITB + i]);
        u = (u & 0x80000000u) ? ~u : (u | 0x80000000u);   // order-preserving
        keys[i] = u;
    }
    if (tid == 0) { sh_kk = TOKB; sh_wpos = 0; sh_naux = 0; sh_eq = 0; }
    if (tid < 256) hist[tid] = 0;
    __syncthreads();
    // pass 1: byte 3
    for (int i = tid; i < NCAND; i += 512) atomicAdd(&hist[keys[i] >> 24], 1);
    __syncthreads();
    scan_pick(hist, warpsums, &sh_bin, &sh_kk, tid);
    unsigned b3 = (unsigned)sh_bin;
    if (tid < 256) hist[tid] = 0;
    __syncthreads();
    // pass 2: byte 2 among prefix matches
    for (int i = tid; i < NCAND; i += 512) {
        unsigned u = keys[i];
        if ((u >> 24) == b3) atomicAdd(&hist[(u >> 16) & 255], 1);
    }
    __syncthreads();
    scan_pick(hist, warpsums, &sh_bin, &sh_kk, tid);
    unsigned prefix16 = (b3 << 8) | (unsigned)sh_bin;
    int* sel = g_sel + bh * TOKB;
    unsigned* aux = g_aux + (size_t)bh * 7936;
    // compaction: definite winners out, ties on prefix16 packed to aux
    for (int i = tid; i < NCAND; i += 512) {
        unsigned u = keys[i];
        unsigned t16 = u >> 16;
        if (t16 > prefix16)       sel[atomicAdd(&sh_wpos, 1)] = INITB + i;
        else if (t16 == prefix16) aux[atomicAdd(&sh_naux, 1)] = ((u & 0xFFFFu) << 13) | (unsigned)i;
    }
    __syncthreads();
    int naux = sh_naux;
    if (tid < 256) hist[tid] = 0;
    __syncthreads();
    // pass 3: key16 high byte
    for (int i = tid; i < naux; i += 512) atomicAdd(&hist[(aux[i] >> 21) & 255], 1);
    __syncthreads();
    scan_pick(hist, warpsums, &sh_bin, &sh_kk, tid);
    unsigned bh8 = (unsigned)sh_bin;
    if (tid < 256) hist[tid] = 0;
    __syncthreads();
    // pass 4: key16 low byte among matches
    for (int i = tid; i < naux; i += 512) {
        unsigned pk_ = aux[i];
        if (((pk_ >> 21) & 255) == bh8) atomicAdd(&hist[(pk_ >> 13) & 255], 1);
    }
    __syncthreads();
    scan_pick(hist, warpsums, &sh_bin, &sh_kk, tid);
    unsigned tau16 = (bh8 << 8) | (unsigned)sh_bin;
    int needeq = sh_kk;
    for (int i = tid; i < naux; i += 512) {
        unsigned pk_ = aux[i];
        unsigned k16 = pk_ >> 13;
        if (k16 > tau16) {
            sel[atomicAdd(&sh_wpos, 1)] = INITB + (int)(pk_ & 0x1FFFu);
        } else if (k16 == tau16) {
            if (atomicAdd(&sh_eq, 1) < needeq)
                sel[atomicAdd(&sh_wpos, 1)] = INITB + (int)(pk_ & 0x1FFFu);
        }
    }
}

// ------------- Kernel 5: softmax over 516 kept + weighted V gather (4-row unroll) -------------
__global__ void attnv_kernel(const float* __restrict__ pv) {
    int bh = blockIdx.x;
    int b = bh >> 5, hq = bh & 31, hkv = hq >> 2;
    int tid = threadIdx.x, warp = tid >> 5, lane = tid & 31;
    __shared__ float sc[NKEEP];
    __shared__ int   idxsh[NKEEP];
    __shared__ float red[8];
    __shared__ float M_sh, Z_sh;
    __shared__ float outsh[8 * 128];
    const float* srow = g_scores + (size_t)bh * SSTRIDE;
    const int* sel = g_sel + bh * TOKB;
    for (int i = tid; i < NKEEP; i += 256) {
        int p;
        if (i < INITB) p = i;
        else if (i < INITB + TOKB) p = sel[i - INITB];
        else p = (KVLEN - RECB) + (i - INITB - TOKB);
        idxsh[i] = p;
        sc[i] = srow[p];
    }
    __syncthreads();
    float m = -INFINITY;
    for (int i = tid; i < NKEEP; i += 256) m = fmaxf(m, sc[i]);
    m = warpmax(m);
    if (lane == 0) red[warp] = m;
    __syncthreads();
    if (tid == 0) {
        float mm = red[0];
        #pragma unroll
        for (int w = 1; w < 8; w++) mm = fmaxf(mm, red[w]);
        M_sh = mm;
    }
    __syncthreads();
    float M = M_sh, z = 0.f;
    for (int i = tid; i < NKEEP; i += 256) {
        float e = __expf(sc[i] - M);
        sc[i] = e;
        z += e;
    }
    z = warpsum(z);
    if (lane == 0) red[warp] = z;
    __syncthreads();
    if (tid == 0) {
        float zz = 0.f;
        #pragma unroll
        for (int w = 0; w < 8; w++) zz += red[w];
        Z_sh = zz;
    }
    __syncthreads();
    float inv = 1.0f / Z_sh;
    float4 acc = make_float4(0.f, 0.f, 0.f, 0.f);
    const float* vbase = pv + ((size_t)(b * HKV_ + hkv) << 20);
    const float* vnrow = g_vnew + (b * HKV_ + hkv) * D_;
    for (int i = warp; i < NKEEP; i += 32) {
        float ww[4];
        const float* vp[4];
        #pragma unroll
        for (int u = 0; u < 4; u++) {
            int ii = i + u * 8;
            bool vld = ii < NKEEP;
            int p = vld ? idxsh[ii] : 0;
            ww[u] = vld ? sc[ii] * inv : 0.f;
            vp[u] = (p < SPAST) ? (vbase + ((size_t)p << 7)) : vnrow;
        }
        float4 v0 = *(const float4*)(vp[0] + lane * 4);
        float4 v1 = *(const float4*)(vp[1] + lane * 4);
        float4 v2 = *(const float4*)(vp[2] + lane * 4);
        float4 v3 = *(const float4*)(vp[3] + lane * 4);
        acc.x = fmaf(ww[0], v0.x, acc.x); acc.y = fmaf(ww[0], v0.y, acc.y);
        acc.z = fmaf(ww[0], v0.z, acc.z); acc.w = fmaf(ww[0], v0.w, acc.w);
        acc.x = fmaf(ww[1], v1.x, acc.x); acc.y = fmaf(ww[1], v1.y, acc.y);
        acc.z = fmaf(ww[1], v1.z, acc.z); acc.w = fmaf(ww[1], v1.w, acc.w);
        acc.x = fmaf(ww[2], v2.x, acc.x); acc.y = fmaf(ww[2], v2.y, acc.y);
        acc.z = fmaf(ww[2], v2.z, acc.z); acc.w = fmaf(ww[2], v2.w, acc.w);
        acc.x = fmaf(ww[3], v3.x, acc.x); acc.y = fmaf(ww[3], v3.y, acc.y);
        acc.z = fmaf(ww[3], v3.z, acc.z); acc.w = fmaf(ww[3], v3.w, acc.w);
    }
    float* os = outsh + warp * 128 + lane * 4;
    os[0] = acc.x; os[1] = acc.y; os[2] = acc.z; os[3] = acc.w;
    __syncthreads();
    if (tid < 128) {
        float s = 0.f;
        #pragma unroll
        for (int w = 0; w < 8; w++) s += outsh[w * 128 + tid];
        g_attn[bh * D_ + tid] = s;
    }
}

// ------------- Kernel 6: output projection GEMV (split-K, float4) -------------
// grid (8, NSPLIT), block 128. 512 cols x 128-K chunk.
__global__ void out_gemv(const float* __restrict__ wo) {
    __shared__ float sh[512];
    int tid = threadIdx.x;
    int k0 = blockIdx.y * 128;
    for (int i = tid; i < 512; i += 128) {
        int b = i >> 7, k = i & 127;
        sh[i] = g_attn[b * HID + k0 + k];
    }
    __syncthreads();
    int col = blockIdx.x * 512 + tid * 4;
    const float* wp = wo + (size_t)k0 * HID + col;
    float4 a0 = make_float4(0,0,0,0), a1 = a0, a2 = a0, a3 = a0;
    #pragma unroll 8
    for (int k = 0; k < 128; k++) {
        float4 wv4 = *(const float4*)(wp + (size_t)k * HID);
        float h0 = sh[k], h1 = sh[128 + k], h2 = sh[256 + k], h3 = sh[384 + k];
        a0.x = fmaf(h0, wv4.x, a0.x); a0.y = fmaf(h0, wv4.y, a0.y);
        a0.z = fmaf(h0, wv4.z, a0.z); a0.w = fmaf(h0, wv4.w, a0.w);
        a1.x = fmaf(h1, wv4.x, a1.x); a1.y = fmaf(h1, wv4.y, a1.y);
        a1.z = fmaf(h1, wv4.z, a1.z); a1.w = fmaf(h1, wv4.w, a1.w);
        a2.x = fmaf(h2, wv4.x, a2.x); a2.y = fmaf(h2, wv4.y, a2.y);
        a2.z = fmaf(h2, wv4.z, a2.z); a2.w = fmaf(h2, wv4.w, a2.w);
        a3.x = fmaf(h3, wv4.x, a3.x); a3.y = fmaf(h3, wv4.y, a3.y);
        a3.z = fmaf(h3, wv4.z, a3.z); a3.w = fmaf(h3, wv4.w, a3.w);
    }
    float* gp = g_part2 + (size_t)blockIdx.y * (4 * HID);
    *(float4*)(gp + col)           = a0;
    *(float4*)(gp + HID + col)     = a1;
    *(float4*)(gp + 2 * HID + col) = a2;
    *(float4*)(gp + 3 * HID + col) = a3;
}

__global__ void out_reduce(float* __restrict__ out) {
    int idx = blockIdx.x * blockDim.x + threadIdx.x;
    if (idx >= 4 * HID) return;
    int b = idx >> 12, col = idx & 4095;
    float s = 0.f;
    #pragma unroll
    for (int ks = 0; ks < NSPLIT; ks++) s += g_part2[(size_t)ks * (4 * HID) + b * HID + col];
    out[idx] = s;
}

// ------------- launch -------------
extern "C" void kernel_launch(void* const* d_in, const int* in_sizes, int n_in,
                              void* d_out, int out_size) {
    const float* h    = (const float*)d_in[0];
    const float* cosp = (const float*)d_in[1];
    const float* sinp = (const float*)d_in[2];
    const float* pk   = (const float*)d_in[3];
    const float* pv   = (const float*)d_in[4];
    const float* wq   = (const float*)d_in[5];
    const float* wk   = (const float*)d_in[6];
    const float* wv   = (const float*)d_in[7];
    const float* wo   = (const float*)d_in[8];
    float* out = (float*)d_out;

    qkv_gemv<<<dim3(12, NSPLIT), 128>>>(h, wq, wk, wv);
    qkv_reduce<<<(4 * 3584 + 255) / 256, 256>>>(cosp, sinp);
    scores_kernel<<<dim3(33, 32), 256>>>(pk);
    select_kernel<<<128, 512>>>();
    attnv_kernel<<<128, 256>>>(pv);
    out_gemv<<<dim3(8, NSPLIT), 128>>>(wo);
    out_reduce<<<(4 * HID + 255) / 256, 256>>>(out);
}

// round 3
// speedup vs baseline: 2.6510x; 1.1315x over previous
#include <cuda_runtime.h>
#include <math.h>

// Problem constants
#define B_    4
#define HQ_   32
#define HKV_  8
#define D_    128
#define SPAST 8192
#define KVLEN 8193
#define HID   4096
#define NTOT  6144            // 4096 (q) + 1024 (k) + 1024 (v)
#define TOKB  256
#define INITB 4
#define RECB  256
#define NKEEP (INITB + TOKB + RECB)   // 516
#define NCAND 7933            // positions [4, 7936]
#define SSTRIDE 8208
#define SCALE 0.08838834764831845f
#define NSPLIT 32             // split-K factor (K-chunk = 128)

// ------------- scratch (zero-initialized at load; invariants preserved per replay) -------------
__device__ float g_qkv   [4 * NTOT];            // atomically accumulated; re-zeroed by qkv_reduce
__device__ float g_q     [B_ * HQ_ * D_];
__device__ float g_knew  [B_ * HKV_ * D_];
__device__ float g_vnew  [B_ * HKV_ * D_];
__device__ float g_scores[B_ * HQ_ * SSTRIDE];  // 4 MB
__device__ int   g_sel   [B_ * HQ_ * TOKB];
__device__ float g_attn  [B_ * HQ_ * D_];
__device__ unsigned g_auxk[B_ * HQ_ * 7936];    // compacted candidate keys
__device__ int      g_auxi[B_ * HQ_ * 7936];    // compacted candidate indices

// ------------- helpers -------------
__device__ __forceinline__ float warpsum(float v) {
    #pragma unroll
    for (int o = 16; o > 0; o >>= 1) v += __shfl_xor_sync(0xFFFFFFFFu, v, o);
    return v;
}
__device__ __forceinline__ float warpmax(float v) {
    #pragma unroll
    for (int o = 16; o > 0; o >>= 1) v = fmaxf(v, __shfl_xor_sync(0xFFFFFFFFu, v, o));
    return v;
}
__device__ __forceinline__ float dot4(float4 a, float4 b) {
    return a.x * b.x + a.y * b.y + a.z * b.z + a.w * b.w;
}
// fold two per-lane value streams: lanes with (lane&o)==0 end up holding
// lo[l]+lo[l^o]; lanes with bit set hold hi[l]+hi[l^o].
__device__ __forceinline__ float fold(float lo, float hi, int o, int lane) {
    float mine  = (lane & o) ? hi : lo;
    float other = (lane & o) ? lo : hi;
    return mine + __shfl_xor_sync(0xFFFFFFFFu, other, o);
}

// ------------- Kernel 1: QKV GEMV (split-K, float4 weights, atomic accumulate) -------------
// grid (12, NSPLIT), block 128.
__global__ void qkv_gemv(const float* __restrict__ h, const float* __restrict__ wq,
                         const float* __restrict__ wk, const float* __restrict__ wv) {
    __shared__ float sh[512];  // [4 batches][128 k]
    int tid = threadIdx.x;
    int k0 = blockIdx.y * 128;
    for (int i = tid; i < 512; i += 128) {
        int b = i >> 7, k = i & 127;
        sh[i] = h[b * HID + k0 + k];
    }
    __syncthreads();
    int c0 = blockIdx.x * 512;
    const float* w; int stride, col;
    if (c0 < 4096)      { w = wq; stride = 4096; col = c0; }
    else if (c0 < 5120) { w = wk; stride = 1024; col = c0 - 4096; }
    else                { w = wv; stride = 1024; col = c0 - 5120; }
    const float* wp = w + (size_t)k0 * stride + col + tid * 4;
    float4 a0 = make_float4(0,0,0,0), a1 = a0, a2 = a0, a3 = a0;
    #pragma unroll 8
    for (int k = 0; k < 128; k++) {
        float4 wv4 = *(const float4*)(wp + (size_t)k * stride);
        float h0 = sh[k], h1 = sh[128 + k], h2 = sh[256 + k], h3 = sh[384 + k];
        a0.x = fmaf(h0, wv4.x, a0.x); a0.y = fmaf(h0, wv4.y, a0.y);
        a0.z = fmaf(h0, wv4.z, a0.z); a0.w = fmaf(h0, wv4.w, a0.w);
        a1.x = fmaf(h1, wv4.x, a1.x); a1.y = fmaf(h1, wv4.y, a1.y);
        a1.z = fmaf(h1, wv4.z, a1.z); a1.w = fmaf(h1, wv4.w, a1.w);
        a2.x = fmaf(h2, wv4.x, a2.x); a2.y = fmaf(h2, wv4.y, a2.y);
        a2.z = fmaf(h2, wv4.z, a2.z); a2.w = fmaf(h2, wv4.w, a2.w);
        a3.x = fmaf(h3, wv4.x, a3.x); a3.y = fmaf(h3, wv4.y, a3.y);
        a3.z = fmaf(h3, wv4.z, a3.z); a3.w = fmaf(h3, wv4.w, a3.w);
    }
    int c = c0 + tid * 4;
    atomicAdd(&g_qkv[c],     a0.x); atomicAdd(&g_qkv[c + 1],     a0.y);
    atomicAdd(&g_qkv[c + 2], a0.z); atomicAdd(&g_qkv[c + 3],     a0.w);
    atomicAdd(&g_qkv[NTOT + c],     a1.x); atomicAdd(&g_qkv[NTOT + c + 1], a1.y);
    atomicAdd(&g_qkv[NTOT + c + 2], a1.z); atomicAdd(&g_qkv[NTOT + c + 3], a1.w);
    atomicAdd(&g_qkv[2*NTOT + c],     a2.x); atomicAdd(&g_qkv[2*NTOT + c + 1], a2.y);
    atomicAdd(&g_qkv[2*NTOT + c + 2], a2.z); atomicAdd(&g_qkv[2*NTOT + c + 3], a2.w);
    atomicAdd(&g_qkv[3*NTOT + c],     a3.x); atomicAdd(&g_qkv[3*NTOT + c + 1], a3.y);
    atomicAdd(&g_qkv[3*NTOT + c + 2], a3.z); atomicAdd(&g_qkv[3*NTOT + c + 3], a3.w);
}

// ------------- Kernel 2: RoPE on accumulated qkv, then reset accumulator -------------
__global__ void qkv_reduce(const float* __restrict__ cosp, const float* __restrict__ sinp) {
    int idx = blockIdx.x * blockDim.x + threadIdx.x;
    if (idx >= 4 * 3584) return;
    int b = idx / 3584, r = idx % 3584;
    float* gq = g_qkv + b * NTOT;
    if (r < 2560) {
        int head = r >> 6, d = r & 63;
        int col1 = head * 128 + d, col2 = col1 + 64;
        float s1 = gq[col1], s2 = gq[col2];
        gq[col1] = 0.f; gq[col2] = 0.f;         // reset for next replay
        float c1 = cosp[b * D_ + d],      sn1 = sinp[b * D_ + d];
        float c2 = cosp[b * D_ + d + 64], sn2 = sinp[b * D_ + d + 64];
        float r1 = s1 * c1 - s2 * sn1;
        float r2 = s2 * c2 + s1 * sn2;
        if (head < 32) {
            g_q[(b * HQ_ + head) * D_ + d]      = r1;
            g_q[(b * HQ_ + head) * D_ + d + 64] = r2;
        } else {
            int kh = head - 32;
            g_knew[(b * HKV_ + kh) * D_ + d]      = r1;
            g_knew[(b * HKV_ + kh) * D_ + d + 64] = r2;
        }
    } else {
        int lc = r - 2560;
        float s = gq[5120 + lc];
        gq[5120 + lc] = 0.f;
        g_vnew[b * HKV_ * D_ + lc] = s;
    }
}

// ------------- Kernel 3: scores (warp-per-row, 4-row unroll, fold reduction) -------------
// grid (33, 32): blockIdx.y = b*8+hkv, 256-position chunk. 256 threads.
__global__ void scores_kernel(const float* __restrict__ pk) {
    int bh = blockIdx.y;
    int b = bh >> 3, hkv = bh & 7;
    int tid = threadIdx.x, warp = tid >> 5, lane = tid & 31;
    __shared__ float qsh[512];
    const float* qsrc = g_q + (size_t)(b * HQ_ + hkv * 4) * D_;
    for (int i = tid; i < 512; i += 256) qsh[i] = qsrc[i];
    __syncthreads();
    float4 q0 = *(const float4*)(qsh +   0 + lane * 4);
    float4 q1 = *(const float4*)(qsh + 128 + lane * 4);
    float4 q2 = *(const float4*)(qsh + 256 + lane * 4);
    float4 q3 = *(const float4*)(qsh + 384 + lane * 4);
    int base = blockIdx.x * 256;
    float* srow = g_scores + (size_t)(b * HQ_ + hkv * 4) * SSTRIDE;
    const float* kbase = pk + ((size_t)bh << 20);
    const float* knrow = g_knew + bh * D_;
    // result slot for this lane after the fold network:
    int rr = ((lane >> 4) & 1) * 2 + ((lane >> 3) & 1);
    int hh = ((lane >> 2) & 1) * 2 + ((lane >> 1) & 1);
    int p0 = base + warp * 32;
    for (int j = 0; j < 32; j += 4) {
        int p = p0 + j;
        if (p >= KVLEN) break;
        const float* r0p = (p     < SPAST) ? kbase + ((size_t) p      << 7) : knrow;
        const float* r1p = (p + 1 < SPAST) ? kbase + ((size_t)(p + 1) << 7) : knrow;
        const float* r2p = (p + 2 < SPAST) ? kbase + ((size_t)(p + 2) << 7) : knrow;
        const float* r3p = (p + 3 < SPAST) ? kbase + ((size_t)(p + 3) << 7) : knrow;
        float4 k0v = *(const float4*)(r0p + lane * 4);
        float4 k1v = *(const float4*)(r1p + lane * 4);
        float4 k2v = *(const float4*)(r2p + lane * 4);
        float4 k3v = *(const float4*)(r3p + lane * 4);
        // d[r][h]
        float d00 = dot4(k0v, q0), d01 = dot4(k0v, q1), d02 = dot4(k0v, q2), d03 = dot4(k0v, q3);
        float d10 = dot4(k1v, q0), d11 = dot4(k1v, q1), d12 = dot4(k1v, q2), d13 = dot4(k1v, q3);
        float d20 = dot4(k2v, q0), d21 = dot4(k2v, q1), d22 = dot4(k2v, q2), d23 = dot4(k2v, q3);
        float d30 = dot4(k3v, q0), d31 = dot4(k3v, q1), d32 = dot4(k3v, q2), d33 = dot4(k3v, q3);
        // fold r-bit1 (o=16): t[r0][h]
        float t00 = fold(d00, d20, 16, lane), t01 = fold(d01, d21, 16, lane);
        float t02 = fold(d02, d22, 16, lane), t03 = fold(d03, d23, 16, lane);
        float t10 = fold(d10, d30, 16, lane), t11 = fold(d11, d31, 16, lane);
        float t12 = fold(d12, d32, 16, lane), t13 = fold(d13, d33, 16, lane);
        // fold r-bit0 (o=8): u[h]
        float u0 = fold(t00, t10, 8, lane), u1 = fold(t01, t11, 8, lane);
        float u2 = fold(t02, t12, 8, lane), u3 = fold(t03, t13, 8, lane);
        // fold h-bit1 (o=4), h-bit0 (o=2)
        float w0 = fold(u0, u2, 4, lane), w1 = fold(u1, u3, 4, lane);
        float x = fold(w0, w1, 2, lane);
        x += __shfl_xor_sync(0xFFFFFFFFu, x, 1);
        if ((lane & 1) == 0 && p + rr < KVLEN)
            srow[hh * SSTRIDE + p + rr] = x * SCALE;
    }
}

// ------------- Kernel 4: top-256 exact radix select, early compaction -------------
__device__ __forceinline__ void scan_pick(int* hist, int* warpsums, int* sh_bin,
                                          int* sh_kk, int tid) {
    int kk = *sh_kk;
    int v = 0;
    if (tid < 256) {
        int bin = 255 - tid;
        v = hist[bin];
        int lane = tid & 31, w = tid >> 5;
        #pragma unroll
        for (int o = 1; o < 32; o <<= 1) {
            int n = __shfl_up_sync(0xFFFFFFFFu, v, o);
            if (lane >= o) v += n;
        }
        if (lane == 31) warpsums[w] = v;
    }
    __syncthreads();
    if (tid == 0) {
        int a = 0;
        #pragma unroll
        for (int w = 0; w < 8; w++) { int t = warpsums[w]; warpsums[w] = a; a += t; }
    }
    __syncthreads();
    if (tid < 256) {
        v += warpsums[tid >> 5];
        int prev = v - hist[255 - tid];
        if (v >= kk && prev < kk) { *sh_bin = 255 - tid; *sh_kk = kk - prev; }
    }
    __syncthreads();
}

__global__ void select_kernel() {
    __shared__ unsigned keys[NCAND];
    __shared__ int hist[256];
    __shared__ int warpsums[8];
    __shared__ int sh_bin, sh_kk, sh_wpos, sh_naux, sh_eq;
    int bh = blockIdx.x, tid = threadIdx.x;
    const float* srow = g_scores + (size_t)bh * SSTRIDE;
    if (tid == 0) { sh_kk = TOKB; sh_wpos = 0; sh_naux = 0; sh_eq = 0; }
    if (tid < 256) hist[tid] = 0;
    __syncthreads();
    // sweep 1: load keys + pass-A histogram (top byte) fused
    for (int i = tid; i < NCAND; i += 512) {
        unsigned u = __float_as_uint(srow[INITB + i]);
        u = (u & 0x80000000u) ? ~u : (u | 0x80000000u);   // order-preserving
        keys[i] = u;
        atomicAdd(&hist[u >> 24], 1);
    }
    __syncthreads();
    scan_pick(hist, warpsums, &sh_bin, &sh_kk, tid);
    unsigned b3 = (unsigned)sh_bin;
    int* sel = g_sel + bh * TOKB;
    unsigned* auxk = g_auxk + (size_t)bh * 7936;
    int*      auxi = g_auxi + (size_t)bh * 7936;
    // sweep 2: definite winners out, candidates in chosen bin compacted
    for (int i = tid; i < NCAND; i += 512) {
        unsigned u = keys[i];
        unsigned t8 = u >> 24;
        if (t8 > b3) {
            sel[atomicAdd(&sh_wpos, 1)] = INITB + i;
        } else if (t8 == b3) {
            int a = atomicAdd(&sh_naux, 1);
            auxk[a] = u; auxi[a] = i;
        }
    }
    __syncthreads();
    int naux = sh_naux;
    // pass B: byte 2 over compacted set (all share top byte)
    if (tid < 256) hist[tid] = 0;
    __syncthreads();
    for (int i = tid; i < naux; i += 512) atomicAdd(&hist[(auxk[i] >> 16) & 255], 1);
    __syncthreads();
    scan_pick(hist, warpsums, &sh_bin, &sh_kk, tid);
    unsigned p16 = (b3 << 8) | (unsigned)sh_bin;
    // pass C: byte 1
    if (tid < 256) hist[tid] = 0;
    __syncthreads();
    for (int i = tid; i < naux; i += 512) {
        unsigned u = auxk[i];
        if ((u >> 16) == p16) atomicAdd(&hist[(u >> 8) & 255], 1);
    }
    __syncthreads();
    scan_pick(hist, warpsums, &sh_bin, &sh_kk, tid);
    unsigned p24 = (p16 << 8) | (unsigned)sh_bin;
    // pass D: byte 0
    if (tid < 256) hist[tid] = 0;
    __syncthreads();
    for (int i = tid; i < naux; i += 512) {
        unsigned u = auxk[i];
        if ((u >> 8) == p24) atomicAdd(&hist[u & 255], 1);
    }
    __syncthreads();
    scan_pick(hist, warpsums, &sh_bin, &sh_kk, tid);
    unsigned tau = (p24 << 8) | (unsigned)sh_bin;
    int needeq = sh_kk;
    // final: winners above tau, exact tie claim at tau
    for (int i = tid; i < naux; i += 512) {
        unsigned u = auxk[i];
        if (u > tau) {
            sel[atomicAdd(&sh_wpos, 1)] = INITB + auxi[i];
        } else if (u == tau) {
            if (atomicAdd(&sh_eq, 1) < needeq)
                sel[atomicAdd(&sh_wpos, 1)] = INITB + auxi[i];
        }
    }
}

// ------------- Kernel 5: softmax over 516 kept + weighted V gather (512 threads) -------------
__global__ void attnv_kernel(const float* __restrict__ pv, float* __restrict__ out) {
    int bh = blockIdx.x;
    int b = bh >> 5, hq = bh & 31, hkv = hq >> 2;
    int tid = threadIdx.x, warp = tid >> 5, lane = tid & 31;
    __shared__ float sc[NKEEP];
    __shared__ int   idxsh[NKEEP];
    __shared__ float red[16];
    __shared__ float M_sh, Z_sh;
    __shared__ float outsh[16 * 128];
    // zero d_out (runs before out_gemv in-stream); out has 16384 floats = 128 blocks x 128
    if (tid < 128) out[bh * 128 + tid] = 0.f;
    const float* srow = g_scores + (size_t)bh * SSTRIDE;
    const int* sel = g_sel + bh * TOKB;
    for (int i = tid; i < NKEEP; i += 512) {
        int p;
        if (i < INITB) p = i;
        else if (i < INITB + TOKB) p = sel[i - INITB];
        else p = (KVLEN - RECB) + (i - INITB - TOKB);
        idxsh[i] = p;
        sc[i] = srow[p];
    }
    __syncthreads();
    float m = -INFINITY;
    for (int i = tid; i < NKEEP; i += 512) m = fmaxf(m, sc[i]);
    m = warpmax(m);
    if (lane == 0) red[warp] = m;
    __syncthreads();
    if (tid == 0) {
        float mm = red[0];
        #pragma unroll
        for (int w = 1; w < 16; w++) mm = fmaxf(mm, red[w]);
        M_sh = mm;
    }
    __syncthreads();
    float M = M_sh, z = 0.f;
    for (int i = tid; i < NKEEP; i += 512) {
        float e = __expf(sc[i] - M);
        sc[i] = e;
        z += e;
    }
    z = warpsum(z);
    if (lane == 0) red[warp] = z;
    __syncthreads();
    if (tid == 0) {
        float zz = 0.f;
        #pragma unroll
        for (int w = 0; w < 16; w++) zz += red[w];
        Z_sh = zz;
    }
    __syncthreads();
    float inv = 1.0f / Z_sh;
    float4 acc = make_float4(0.f, 0.f, 0.f, 0.f);
    const float* vbase = pv + ((size_t)(b * HKV_ + hkv) << 20);
    const float* vnrow = g_vnew + (b * HKV_ + hkv) * D_;
    for (int i = warp; i < NKEEP; i += 64) {
        float ww[4];
        const float* vp[4];
        #pragma unroll
        for (int u = 0; u < 4; u++) {
            int ii = i + u * 16;
            bool vld = ii < NKEEP;
            int p = vld ? idxsh[ii] : 0;
            ww[u] = vld ? sc[ii] * inv : 0.f;
            vp[u] = (p < SPAST) ? (vbase + ((size_t)p << 7)) : vnrow;
        }
        float4 v0 = *(const float4*)(vp[0] + lane * 4);
        float4 v1 = *(const float4*)(vp[1] + lane * 4);
        float4 v2 = *(const float4*)(vp[2] + lane * 4);
        float4 v3 = *(const float4*)(vp[3] + lane * 4);
        acc.x = fmaf(ww[0], v0.x, acc.x); acc.y = fmaf(ww[0], v0.y, acc.y);
        acc.z = fmaf(ww[0], v0.z, acc.z); acc.w = fmaf(ww[0], v0.w, acc.w);
        acc.x = fmaf(ww[1], v1.x, acc.x); acc.y = fmaf(ww[1], v1.y, acc.y);
        acc.z = fmaf(ww[1], v1.z, acc.z); acc.w = fmaf(ww[1], v1.w, acc.w);
        acc.x = fmaf(ww[2], v2.x, acc.x); acc.y = fmaf(ww[2], v2.y, acc.y);
        acc.z = fmaf(ww[2], v2.z, acc.z); acc.w = fmaf(ww[2], v2.w, acc.w);
        acc.x = fmaf(ww[3], v3.x, acc.x); acc.y = fmaf(ww[3], v3.y, acc.y);
        acc.z = fmaf(ww[3], v3.z, acc.z); acc.w = fmaf(ww[3], v3.w, acc.w);
    }
    float* os = outsh + warp * 128 + lane * 4;
    os[0] = acc.x; os[1] = acc.y; os[2] = acc.z; os[3] = acc.w;
    __syncthreads();
    if (tid < 128) {
        float s = 0.f;
        #pragma unroll
        for (int w = 0; w < 16; w++) s += outsh[w * 128 + tid];
        g_attn[bh * D_ + tid] = s;
    }
}

// ------------- Kernel 6: output projection GEMV (split-K, atomic accumulate to d_out) -------------
// grid (8, NSPLIT), block 128.
__global__ void out_gemv(const float* __restrict__ wo, float* __restrict__ out) {
    __shared__ float sh[512];
    int tid = threadIdx.x;
    int k0 = blockIdx.y * 128;
    for (int i = tid; i < 512; i += 128) {
        int b = i >> 7, k = i & 127;
        sh[i] = g_attn[b * HID + k0 + k];
    }
    __syncthreads();
    int col = blockIdx.x * 512 + tid * 4;
    const float* wp = wo + (size_t)k0 * HID + col;
    float4 a0 = make_float4(0,0,0,0), a1 = a0, a2 = a0, a3 = a0;
    #pragma unroll 8
    for (int k = 0; k < 128; k++) {
        float4 wv4 = *(const float4*)(wp + (size_t)k * HID);
        float h0 = sh[k], h1 = sh[128 + k], h2 = sh[256 + k], h3 = sh[384 + k];
        a0.x = fmaf(h0, wv4.x, a0.x); a0.y = fmaf(h0, wv4.y, a0.y);
        a0.z = fmaf(h0, wv4.z, a0.z); a0.w = fmaf(h0, wv4.w, a0.w);
        a1.x = fmaf(h1, wv4.x, a1.x); a1.y = fmaf(h1, wv4.y, a1.y);
        a1.z = fmaf(h1, wv4.z, a1.z); a1.w = fmaf(h1, wv4.w, a1.w);
        a2.x = fmaf(h2, wv4.x, a2.x); a2.y = fmaf(h2, wv4.y, a2.y);
        a2.z = fmaf(h2, wv4.z, a2.z); a2.w = fmaf(h2, wv4.w, a2.w);
        a3.x = fmaf(h3, wv4.x, a3.x); a3.y = fmaf(h3, wv4.y, a3.y);
        a3.z = fmaf(h3, wv4.z, a3.z); a3.w = fmaf(h3, wv4.w, a3.w);
    }
    atomicAdd(&out[col],     a0.x); atomicAdd(&out[col + 1],     a0.y);
    atomicAdd(&out[col + 2], a0.z); atomicAdd(&out[col + 3],     a0.w);
    atomicAdd(&out[HID + col],     a1.x); atomicAdd(&out[HID + col + 1], a1.y);
    atomicAdd(&out[HID + col + 2], a1.z); atomicAdd(&out[HID + col + 3], a1.w);
    atomicAdd(&out[2*HID + col],     a2.x); atomicAdd(&out[2*HID + col + 1], a2.y);
    atomicAdd(&out[2*HID + col + 2], a2.z); atomicAdd(&out[2*HID + col + 3], a2.w);
    atomicAdd(&out[3*HID + col],     a3.x); atomicAdd(&out[3*HID + col + 1], a3.y);
    atomicAdd(&out[3*HID + col + 2], a3.z); atomicAdd(&out[3*HID + col + 3], a3.w);
}

// ------------- launch -------------
extern "C" void kernel_launch(void* const* d_in, const int* in_sizes, int n_in,
                              void* d_out, int out_size) {
    const float* h    = (const float*)d_in[0];
    const float* cosp = (const float*)d_in[1];
    const float* sinp = (const float*)d_in[2];
    const float* pk   = (const float*)d_in[3];
    const float* pv   = (const float*)d_in[4];
    const float* wq   = (const float*)d_in[5];
    const float* wk   = (const float*)d_in[6];
    const float* wv   = (const float*)d_in[7];
    const float* wo   = (const float*)d_in[8];
    float* out = (float*)d_out;

    qkv_gemv<<<dim3(12, NSPLIT), 128>>>(h, wq, wk, wv);
    qkv_reduce<<<(4 * 3584 + 255) / 256, 256>>>(cosp, sinp);
    scores_kernel<<<dim3(33, 32), 256>>>(pk);
    select_kernel<<<128, 512>>>();
    attnv_kernel<<<128, 512>>>(pv, out);
    out_gemv<<<dim3(8, NSPLIT), 128>>>(wo, out);
}

// round 4
// speedup vs baseline: 2.8384x; 1.0707x over previous
#include <cuda_runtime.h>
#include <math.h>

// Problem constants
#define B_    4
#define HQ_   32
#define HKV_  8
#define D_    128
#define SPAST 8192
#define KVLEN 8193
#define HID   4096
#define NTOT  6144            // 4096 (q) + 1024 (k) + 1024 (v)
#define TOKB  256
#define INITB 4
#define RECB  256
#define NKEEP (INITB + TOKB + RECB)   // 516
#define NCAND 7933            // positions [4, 7936]
#define SSTRIDE 8208
#define SCALE 0.08838834764831845f
#define NSPLIT 32

// ------------- scratch (zero-initialized at load; invariants preserved per replay) -------------
__device__ float g_qkv   [4 * NTOT];            // atomically accumulated; re-zeroed by qkv_reduce
__device__ float g_q     [B_ * HQ_ * D_];
__device__ float g_knew  [B_ * HKV_ * D_];
__device__ float g_vnew  [B_ * HKV_ * D_];
__device__ float g_scores[B_ * HQ_ * SSTRIDE];
__device__ int   g_sel   [B_ * HQ_ * TOKB];
__device__ float g_attn  [B_ * HQ_ * D_];

// ------------- helpers -------------
__device__ __forceinline__ float warpsum(float v) {
    #pragma unroll
    for (int o = 16; o > 0; o >>= 1) v += __shfl_xor_sync(0xFFFFFFFFu, v, o);
    return v;
}
__device__ __forceinline__ float warpmax(float v) {
    #pragma unroll
    for (int o = 16; o > 0; o >>= 1) v = fmaxf(v, __shfl_xor_sync(0xFFFFFFFFu, v, o));
    return v;
}
__device__ __forceinline__ float dot4(float4 a, float4 b) {
    return a.x * b.x + a.y * b.y + a.z * b.z + a.w * b.w;
}
__device__ __forceinline__ float fold(float lo, float hi, int o, int lane) {
    float mine  = (lane & o) ? hi : lo;
    float other = (lane & o) ? lo : hi;
    return mine + __shfl_xor_sync(0xFFFFFFFFu, other, o);
}

// ------------- Kernel 1: QKV GEMV (split-K, float4 weights, atomic accumulate) -------------
__global__ void qkv_gemv(const float* __restrict__ h, const float* __restrict__ wq,
                         const float* __restrict__ wk, const float* __restrict__ wv) {
    __shared__ float sh[512];
    int tid = threadIdx.x;
    int k0 = blockIdx.y * 128;
    for (int i = tid; i < 512; i += 128) {
        int b = i >> 7, k = i & 127;
        sh[i] = h[b * HID + k0 + k];
    }
    __syncthreads();
    int c0 = blockIdx.x * 512;
    const float* w; int stride, col;
    if (c0 < 4096)      { w = wq; stride = 4096; col = c0; }
    else if (c0 < 5120) { w = wk; stride = 1024; col = c0 - 4096; }
    else                { w = wv; stride = 1024; col = c0 - 5120; }
    const float* wp = w + (size_t)k0 * stride + col + tid * 4;
    float4 a0 = make_float4(0,0,0,0), a1 = a0, a2 = a0, a3 = a0;
    #pragma unroll 8
    for (int k = 0; k < 128; k++) {
        float4 wv4 = *(const float4*)(wp + (size_t)k * stride);
        float h0 = sh[k], h1 = sh[128 + k], h2 = sh[256 + k], h3 = sh[384 + k];
        a0.x = fmaf(h0, wv4.x, a0.x); a0.y = fmaf(h0, wv4.y, a0.y);
        a0.z = fmaf(h0, wv4.z, a0.z); a0.w = fmaf(h0, wv4.w, a0.w);
        a1.x = fmaf(h1, wv4.x, a1.x); a1.y = fmaf(h1, wv4.y, a1.y);
        a1.z = fmaf(h1, wv4.z, a1.z); a1.w = fmaf(h1, wv4.w, a1.w);
        a2.x = fmaf(h2, wv4.x, a2.x); a2.y = fmaf(h2, wv4.y, a2.y);
        a2.z = fmaf(h2, wv4.z, a2.z); a2.w = fmaf(h2, wv4.w, a2.w);
        a3.x = fmaf(h3, wv4.x, a3.x); a3.y = fmaf(h3, wv4.y, a3.y);
        a3.z = fmaf(h3, wv4.z, a3.z); a3.w = fmaf(h3, wv4.w, a3.w);
    }
    int c = c0 + tid * 4;
    atomicAdd(&g_qkv[c],     a0.x); atomicAdd(&g_qkv[c + 1],     a0.y);
    atomicAdd(&g_qkv[c + 2], a0.z); atomicAdd(&g_qkv[c + 3],     a0.w);
    atomicAdd(&g_qkv[NTOT + c],     a1.x); atomicAdd(&g_qkv[NTOT + c + 1], a1.y);
    atomicAdd(&g_qkv[NTOT + c + 2], a1.z); atomicAdd(&g_qkv[NTOT + c + 3], a1.w);
    atomicAdd(&g_qkv[2*NTOT + c],     a2.x); atomicAdd(&g_qkv[2*NTOT + c + 1], a2.y);
    atomicAdd(&g_qkv[2*NTOT + c + 2], a2.z); atomicAdd(&g_qkv[2*NTOT + c + 3], a2.w);
    atomicAdd(&g_qkv[3*NTOT + c],     a3.x); atomicAdd(&g_qkv[3*NTOT + c + 1], a3.y);
    atomicAdd(&g_qkv[3*NTOT + c + 2], a3.z); atomicAdd(&g_qkv[3*NTOT + c + 3], a3.w);
}

// ------------- Kernel 2: RoPE + accumulator reset -------------
__global__ void qkv_reduce(const float* __restrict__ cosp, const float* __restrict__ sinp) {
    int idx = blockIdx.x * blockDim.x + threadIdx.x;
    if (idx >= 4 * 3584) return;
    int b = idx / 3584, r = idx % 3584;
    float* gq = g_qkv + b * NTOT;
    if (r < 2560) {
        int head = r >> 6, d = r & 63;
        int col1 = head * 128 + d, col2 = col1 + 64;
        float s1 = gq[col1], s2 = gq[col2];
        gq[col1] = 0.f; gq[col2] = 0.f;
        float c1 = cosp[b * D_ + d],      sn1 = sinp[b * D_ + d];
        float c2 = cosp[b * D_ + d + 64], sn2 = sinp[b * D_ + d + 64];
        float r1 = s1 * c1 - s2 * sn1;
        float r2 = s2 * c2 + s1 * sn2;
        if (head < 32) {
            g_q[(b * HQ_ + head) * D_ + d]      = r1;
            g_q[(b * HQ_ + head) * D_ + d + 64] = r2;
        } else {
            int kh = head - 32;
            g_knew[(b * HKV_ + kh) * D_ + d]      = r1;
            g_knew[(b * HKV_ + kh) * D_ + d + 64] = r2;
        }
    } else {
        int lc = r - 2560;
        float s = gq[5120 + lc];
        gq[5120 + lc] = 0.f;
        g_vnew[b * HKV_ * D_ + lc] = s;
    }
}

// ------------- Kernel 3: scores -------------
__global__ void scores_kernel(const float* __restrict__ pk) {
    int bh = blockIdx.y;
    int b = bh >> 3, hkv = bh & 7;
    int tid = threadIdx.x, warp = tid >> 5, lane = tid & 31;
    __shared__ float qsh[512];
    const float* qsrc = g_q + (size_t)(b * HQ_ + hkv * 4) * D_;
    for (int i = tid; i < 512; i += 256) qsh[i] = qsrc[i];
    __syncthreads();
    float4 q0 = *(const float4*)(qsh +   0 + lane * 4);
    float4 q1 = *(const float4*)(qsh + 128 + lane * 4);
    float4 q2 = *(const float4*)(qsh + 256 + lane * 4);
    float4 q3 = *(const float4*)(qsh + 384 + lane * 4);
    int base = blockIdx.x * 256;
    float* srow = g_scores + (size_t)(b * HQ_ + hkv * 4) * SSTRIDE;
    const float* kbase = pk + ((size_t)bh << 20);
    const float* knrow = g_knew + bh * D_;
    int rr = ((lane >> 4) & 1) * 2 + ((lane >> 3) & 1);
    int hh = ((lane >> 2) & 1) * 2 + ((lane >> 1) & 1);
    int p0 = base + warp * 32;
    bool fast = (p0 + 31 < SPAST);
    if (fast) {
        #pragma unroll 2
        for (int j = 0; j < 32; j += 4) {
            int p = p0 + j;
            const float* rp = kbase + ((size_t)p << 7) + lane * 4;
            float4 k0v = *(const float4*)(rp);
            float4 k1v = *(const float4*)(rp + 128);
            float4 k2v = *(const float4*)(rp + 256);
            float4 k3v = *(const float4*)(rp + 384);
            float d00 = dot4(k0v, q0), d01 = dot4(k0v, q1), d02 = dot4(k0v, q2), d03 = dot4(k0v, q3);
            float d10 = dot4(k1v, q0), d11 = dot4(k1v, q1), d12 = dot4(k1v, q2), d13 = dot4(k1v, q3);
            float d20 = dot4(k2v, q0), d21 = dot4(k2v, q1), d22 = dot4(k2v, q2), d23 = dot4(k2v, q3);
            float d30 = dot4(k3v, q0), d31 = dot4(k3v, q1), d32 = dot4(k3v, q2), d33 = dot4(k3v, q3);
            float t00 = fold(d00, d20, 16, lane), t01 = fold(d01, d21, 16, lane);
            float t02 = fold(d02, d22, 16, lane), t03 = fold(d03, d23, 16, lane);
            float t10 = fold(d10, d30, 16, lane), t11 = fold(d11, d31, 16, lane);
            float t12 = fold(d12, d32, 16, lane), t13 = fold(d13, d33, 16, lane);
            float u0 = fold(t00, t10, 8, lane), u1 = fold(t01, t11, 8, lane);
            float u2 = fold(t02, t12, 8, lane), u3 = fold(t03, t13, 8, lane);
            float w0 = fold(u0, u2, 4, lane), w1 = fold(u1, u3, 4, lane);
            float x = fold(w0, w1, 2, lane);
            x += __shfl_xor_sync(0xFFFFFFFFu, x, 1);
            if ((lane & 1) == 0)
                srow[hh * SSTRIDE + p + rr] = x * SCALE;
        }
    } else {
        for (int j = 0; j < 32; j += 4) {
            int p = p0 + j;
            if (p >= KVLEN) break;
            const float* r0p = (p     < SPAST) ? kbase + ((size_t) p      << 7) : knrow;
            const float* r1p = (p + 1 < SPAST) ? kbase + ((size_t)(p + 1) << 7) : knrow;
            const float* r2p = (p + 2 < SPAST) ? kbase + ((size_t)(p + 2) << 7) : knrow;
            const float* r3p = (p + 3 < SPAST) ? kbase + ((size_t)(p + 3) << 7) : knrow;
            float4 k0v = *(const float4*)(r0p + lane * 4);
            float4 k1v = *(const float4*)(r1p + lane * 4);
            float4 k2v = *(const float4*)(r2p + lane * 4);
            float4 k3v = *(const float4*)(r3p + lane * 4);
            float d00 = dot4(k0v, q0), d01 = dot4(k0v, q1), d02 = dot4(k0v, q2), d03 = dot4(k0v, q3);
            float d10 = dot4(k1v, q0), d11 = dot4(k1v, q1), d12 = dot4(k1v, q2), d13 = dot4(k1v, q3);
            float d20 = dot4(k2v, q0), d21 = dot4(k2v, q1), d22 = dot4(k2v, q2), d23 = dot4(k2v, q3);
            float d30 = dot4(k3v, q0), d31 = dot4(k3v, q1), d32 = dot4(k3v, q2), d33 = dot4(k3v, q3);
            float t00 = fold(d00, d20, 16, lane), t01 = fold(d01, d21, 16, lane);
            float t02 = fold(d02, d22, 16, lane), t03 = fold(d03, d23, 16, lane);
            float t10 = fold(d10, d30, 16, lane), t11 = fold(d11, d31, 16, lane);
            float t12 = fold(d12, d32, 16, lane), t13 = fold(d13, d33, 16, lane);
            float u0 = fold(t00, t10, 8, lane), u1 = fold(t01, t11, 8, lane);
            float u2 = fold(t02, t12, 8, lane), u3 = fold(t03, t13, 8, lane);
            float w0 = fold(u0, u2, 4, lane), w1 = fold(u1, u3, 4, lane);
            float x = fold(w0, w1, 2, lane);
            x += __shfl_xor_sync(0xFFFFFFFFu, x, 1);
            if ((lane & 1) == 0 && p + rr < KVLEN)
                srow[hh * SSTRIDE + p + rr] = x * SCALE;
        }
    }
}

// ------------- Kernel 4: top-256 exact radix select, register-resident keys -------------
// 512 threads, 16 keys/thread in registers. One global sweep.
// Level 1: 2048 bins (key>>21). Levels 2-4: 256/256/32 bins over register keys only.
#define KPT 16
__device__ __forceinline__ void scan_pick256(int* hist, int* warpsums, int* sh_bin,
                                             int* sh_kk, int tid, int nbins) {
    int kk = *sh_kk;
    int v = 0;
    if (tid < nbins) {
        int bin = nbins - 1 - tid;
        v = hist[bin];
        int lane = tid & 31;
        #pragma unroll
        for (int o = 1; o < 32; o <<= 1) {
            int n = __shfl_up_sync(0xFFFFFFFFu, v, o);
            if (lane >= o) v += n;
        }
        if (lane == 31) warpsums[tid >> 5] = v;
    }
    __syncthreads();
    if (tid == 0) {
        int a = 0;
        for (int w = 0; w < (nbins >> 5); w++) { int t = warpsums[w]; warpsums[w] = a; a += t; }
    }
    __syncthreads();
    if (tid < nbins) {
        v += warpsums[tid >> 5];
        int prev = v - hist[nbins - 1 - tid];
        if (v >= kk && prev < kk) { *sh_bin = nbins - 1 - tid; *sh_kk = kk - prev; }
    }
    __syncthreads();
}

__global__ void select_kernel() {
    __shared__ int hist[2048];
    __shared__ int warpsums[16];
    __shared__ int sh_bin, sh_kk, sh_wpos, sh_eq;
    int bh = blockIdx.x, tid = threadIdx.x;
    const float* srow = g_scores + (size_t)bh * SSTRIDE;
    unsigned key[KPT];
    // clear 2048-bin hist
    #pragma unroll
    for (int j = 0; j < 4; j++) hist[tid + j * 512] = 0;
    if (tid == 0) { sh_kk = TOKB; sh_wpos = 0; sh_eq = 0; }
    __syncthreads();
    // one global sweep: load + level-1 histogram
    #pragma unroll
    for (int j = 0; j < KPT; j++) {
        int i = tid + j * 512;
        unsigned u = 0;
        if (i < NCAND) {
            u = __float_as_uint(srow[INITB + i]);
            u = (u & 0x80000000u) ? ~u : (u | 0x80000000u);
            atomicAdd(&hist[u >> 21], 1);
        }
        key[j] = u;   // u==0 never selected (smaller than any real key)
    }
    __syncthreads();
    // level-1 scan over 2048 reversed bins: thread t covers bins 2047-4t .. 2047-4t-3
    {
        int kk = sh_kk;
        int b0 = 2047 - tid * 4;
        int c0 = hist[b0], c1 = hist[b0 - 1], c2 = hist[b0 - 2], c3 = hist[b0 - 3];
        int s = c0 + c1 + c2 + c3;
        int v = s;
        int lane = tid & 31;
        #pragma unroll
        for (int o = 1; o < 32; o <<= 1) {
            int n = __shfl_up_sync(0xFFFFFFFFu, v, o);
            if (lane >= o) v += n;
        }
        if (lane == 31) warpsums[tid >> 5] = v;
        __syncthreads();
        if (tid == 0) {
            int a = 0;
            #pragma unroll
            for (int w = 0; w < 16; w++) { int t = warpsums[w]; warpsums[w] = a; a += t; }
        }
        __syncthreads();
        int excl = v - s + warpsums[tid >> 5];
        if (excl < kk && excl + s >= kk) {
            int c[4] = {c0, c1, c2, c3};
            int acc = excl;
            #pragma unroll
            for (int q = 0; q < 4; q++) {
                if (acc < kk && acc + c[q] >= kk) { sh_bin = b0 - q; sh_kk = kk - acc; break; }
                acc += c[q];
            }
        }
        __syncthreads();
    }
    unsigned B1 = (unsigned)sh_bin;
    int* sel = g_sel + bh * TOKB;
    // level-1 classify: winners out, candidates keep; level-2 hist (256 bins)
    if (tid < 256) hist[tid] = 0;
    __syncthreads();
    #pragma unroll
    for (int j = 0; j < KPT; j++) {
        int i = tid + j * 512;
        if (i < NCAND) {
            unsigned t = key[j] >> 21;
            if (t > B1) sel[atomicAdd(&sh_wpos, 1)] = INITB + i;
            else if (t == B1) atomicAdd(&hist[(key[j] >> 13) & 255], 1);
        }
    }
    __syncthreads();
    scan_pick256(hist, warpsums, &sh_bin, &sh_kk, tid, 256);
    unsigned P2 = (B1 << 8) | (unsigned)sh_bin;
    // level-2 classify + level-3 hist
    if (tid < 256) hist[tid] = 0;
    __syncthreads();
    #pragma unroll
    for (int j = 0; j < KPT; j++) {
        int i = tid + j * 512;
        if (i < NCAND && (key[j] >> 21) == B1) {
            unsigned t = key[j] >> 13;
            if (t > P2) sel[atomicAdd(&sh_wpos, 1)] = INITB + i;
            else if (t == P2) atomicAdd(&hist[(key[j] >> 5) & 255], 1);
        }
    }
    __syncthreads();
    scan_pick256(hist, warpsums, &sh_bin, &sh_kk, tid, 256);
    unsigned P3 = (P2 << 8) | (unsigned)sh_bin;
    // level-3 classify + level-4 hist (32 bins)
    if (tid < 32) hist[tid] = 0;
    __syncthreads();
    #pragma unroll
    for (int j = 0; j < KPT; j++) {
        int i = tid + j * 512;
        if (i < NCAND && (key[j] >> 13) == P2) {
            unsigned t = key[j] >> 5;
            if (t > P3) sel[atomicAdd(&sh_wpos, 1)] = INITB + i;
            else if (t == P3) atomicAdd(&hist[key[j] & 31], 1);
        }
    }
    __syncthreads();
    scan_pick256(hist, warpsums, &sh_bin, &sh_kk, tid, 32);
    unsigned tau = (P3 << 5) | (unsigned)sh_bin;
    int needeq = sh_kk;
    // final: winners above tau + exact tie claim
    #pragma unroll
    for (int j = 0; j < KPT; j++) {
        int i = tid + j * 512;
        if (i < NCAND && (key[j] >> 5) == P3) {
            if (key[j] > tau) sel[atomicAdd(&sh_wpos, 1)] = INITB + i;
            else if (key[j] == tau) {
                if (atomicAdd(&sh_eq, 1) < needeq)
                    sel[atomicAdd(&sh_wpos, 1)] = INITB + i;
            }
        }
    }
}

// ------------- Kernel 5: softmax + weighted V gather -------------
__global__ void attnv_kernel(const float* __restrict__ pv, float* __restrict__ out) {
    int bh = blockIdx.x;
    int b = bh >> 5, hq = bh & 31, hkv = hq >> 2;
    int tid = threadIdx.x, warp = tid >> 5, lane = tid & 31;
    __shared__ float sc[NKEEP];
    __shared__ int   idxsh[NKEEP];
    __shared__ float red[16];
    __shared__ float M_sh, Z_sh;
    __shared__ float outsh[16 * 128];
    if (tid < 128) out[bh * 128 + tid] = 0.f;   // zero d_out ahead of out_gemv
    const float* srow = g_scores + (size_t)bh * SSTRIDE;
    const int* sel = g_sel + bh * TOKB;
    for (int i = tid; i < NKEEP; i += 512) {
        int p;
        if (i < INITB) p = i;
        else if (i < INITB + TOKB) p = sel[i - INITB];
        else p = (KVLEN - RECB) + (i - INITB - TOKB);
        idxsh[i] = p;
        sc[i] = srow[p];
    }
    __syncthreads();
    float m = -INFINITY;
    for (int i = tid; i < NKEEP; i += 512) m = fmaxf(m, sc[i]);
    m = warpmax(m);
    if (lane == 0) red[warp] = m;
    __syncthreads();
    if (tid == 0) {
        float mm = red[0];
        #pragma unroll
        for (int w = 1; w < 16; w++) mm = fmaxf(mm, red[w]);
        M_sh = mm;
    }
    __syncthreads();
    float M = M_sh, z = 0.f;
    for (int i = tid; i < NKEEP; i += 512) {
        float e = __expf(sc[i] - M);
        sc[i] = e;
        z += e;
    }
    z = warpsum(z);
    if (lane == 0) red[warp] = z;
    __syncthreads();
    if (tid == 0) {
        float zz = 0.f;
        #pragma unroll
        for (int w = 0; w < 16; w++) zz += red[w];
        Z_sh = zz;
    }
    __syncthreads();
    float inv = 1.0f / Z_sh;
    float4 acc = make_float4(0.f, 0.f, 0.f, 0.f);
    const float* vbase = pv + ((size_t)(b * HKV_ + hkv) << 20);
    const float* vnrow = g_vnew + (b * HKV_ + hkv) * D_;
    for (int i = warp; i < NKEEP; i += 64) {
        float ww[4];
        const float* vp[4];
        #pragma unroll
        for (int u = 0; u < 4; u++) {
            int ii = i + u * 16;
            bool vld = ii < NKEEP;
            int p = vld ? idxsh[ii] : 0;
            ww[u] = vld ? sc[ii] * inv : 0.f;
            vp[u] = (p < SPAST) ? (vbase + ((size_t)p << 7)) : vnrow;
        }
        float4 v0 = *(const float4*)(vp[0] + lane * 4);
        float4 v1 = *(const float4*)(vp[1] + lane * 4);
        float4 v2 = *(const float4*)(vp[2] + lane * 4);
        float4 v3 = *(const float4*)(vp[3] + lane * 4);
        acc.x = fmaf(ww[0], v0.x, acc.x); acc.y = fmaf(ww[0], v0.y, acc.y);
        acc.z = fmaf(ww[0], v0.z, acc.z); acc.w = fmaf(ww[0], v0.w, acc.w);
        acc.x = fmaf(ww[1], v1.x, acc.x); acc.y = fmaf(ww[1], v1.y, acc.y);
        acc.z = fmaf(ww[1], v1.z, acc.z); acc.w = fmaf(ww[1], v1.w, acc.w);
        acc.x = fmaf(ww[2], v2.x, acc.x); acc.y = fmaf(ww[2], v2.y, acc.y);
        acc.z = fmaf(ww[2], v2.z, acc.z); acc.w = fmaf(ww[2], v2.w, acc.w);
        acc.x = fmaf(ww[3], v3.x, acc.x); acc.y = fmaf(ww[3], v3.y, acc.y);
        acc.z = fmaf(ww[3], v3.z, acc.z); acc.w = fmaf(ww[3], v3.w, acc.w);
    }
    float* os = outsh + warp * 128 + lane * 4;
    os[0] = acc.x; os[1] = acc.y; os[2] = acc.z; os[3] = acc.w;
    __syncthreads();
    if (tid < 128) {
        float s = 0.f;
        #pragma unroll
        for (int w = 0; w < 16; w++) s += outsh[w * 128 + tid];
        g_attn[bh * D_ + tid] = s;
    }
}

// ------------- Kernel 6: output projection GEMV (split-K, atomic accumulate) -------------
__global__ void out_gemv(const float* __restrict__ wo, float* __restrict__ out) {
    __shared__ float sh[512];
    int tid = threadIdx.x;
    int k0 = blockIdx.y * 128;
    for (int i = tid; i < 512; i += 128) {
        int b = i >> 7, k = i & 127;
        sh[i] = g_attn[b * HID + k0 + k];
    }
    __syncthreads();
    int col = blockIdx.x * 512 + tid * 4;
    const float* wp = wo + (size_t)k0 * HID + col;
    float4 a0 = make_float4(0,0,0,0), a1 = a0, a2 = a0, a3 = a0;
    #pragma unroll 8
    for (int k = 0; k < 128; k++) {
        float4 wv4 = *(const float4*)(wp + (size_t)k * HID);
        float h0 = sh[k], h1 = sh[128 + k], h2 = sh[256 + k], h3 = sh[384 + k];
        a0.x = fmaf(h0, wv4.x, a0.x); a0.y = fmaf(h0, wv4.y, a0.y);
        a0.z = fmaf(h0, wv4.z, a0.z); a0.w = fmaf(h0, wv4.w, a0.w);
        a1.x = fmaf(h1, wv4.x, a1.x); a1.y = fmaf(h1, wv4.y, a1.y);
        a1.z = fmaf(h1, wv4.z, a1.z); a1.w = fmaf(h1, wv4.w, a1.w);
        a2.x = fmaf(h2, wv4.x, a2.x); a2.y = fmaf(h2, wv4.y, a2.y);
        a2.z = fmaf(h2, wv4.z, a2.z); a2.w = fmaf(h2, wv4.w, a2.w);
        a3.x = fmaf(h3, wv4.x, a3.x); a3.y = fmaf(h3, wv4.y, a3.y);
        a3.z = fmaf(h3, wv4.z, a3.z); a3.w = fmaf(h3, wv4.w, a3.w);
    }
    atomicAdd(&out[col],     a0.x); atomicAdd(&out[col + 1],     a0.y);
    atomicAdd(&out[col + 2], a0.z); atomicAdd(&out[col + 3],     a0.w);
    atomicAdd(&out[HID + col],     a1.x); atomicAdd(&out[HID + col + 1], a1.y);
    atomicAdd(&out[HID + col + 2], a1.z); atomicAdd(&out[HID + col + 3], a1.w);
    atomicAdd(&out[2*HID + col],     a2.x); atomicAdd(&out[2*HID + col + 1], a2.y);
    atomicAdd(&out[2*HID + col + 2], a2.z); atomicAdd(&out[2*HID + col + 3], a2.w);
    atomicAdd(&out[3*HID + col],     a3.x); atomicAdd(&out[3*HID + col + 1], a3.y);
    atomicAdd(&out[3*HID + col + 2], a3.z); atomicAdd(&out[3*HID + col + 3], a3.w);
}

// ------------- launch -------------
extern "C" void kernel_launch(void* const* d_in, const int* in_sizes, int n_in,
                              void* d_out, int out_size) {
    const float* h    = (const float*)d_in[0];
    const float* cosp = (const float*)d_in[1];
    const float* sinp = (const float*)d_in[2];
    const float* pk   = (const float*)d_in[3];
    const float* pv   = (const float*)d_in[4];
    const float* wq   = (const float*)d_in[5];
    const float* wk   = (const float*)d_in[6];
    const float* wv   = (const float*)d_in[7];
    const float* wo   = (const float*)d_in[8];
    float* out = (float*)d_out;

    qkv_gemv<<<dim3(12, NSPLIT), 128>>>(h, wq, wk, wv);
    qkv_reduce<<<(4 * 3584 + 255) / 256, 256>>>(cosp, sinp);
    scores_kernel<<<dim3(33, 32), 256>>>(pk);
    select_kernel<<<128, 512>>>();
    attnv_kernel<<<128, 512>>>(pv, out);
    out_gemv<<<dim3(8, NSPLIT), 128>>>(wo, out);
}

// round 6
// speedup vs baseline: 3.5375x; 1.2463x over previous
#include <cuda_runtime.h>
#include <math.h>

// Problem constants
#define B_    4
#define HQ_   32
#define HKV_  8
#define D_    128
#define SPAST 8192
#define KVLEN 8193
#define HID   4096
#define NTOT  6144            // 4096 (q) + 1024 (k) + 1024 (v)
#define TOKB  256
#define INITB 4
#define RECB  256
#define NKEEP (INITB + TOKB + RECB)   // 516
#define NCAND 7933            // positions [4, 7936]
#define SSTRIDE 8208
#define SCALE 0.08838834764831845f
#define NSPLIT 64             // split-K factor (K-chunk = 64)

// ------------- scratch (zero-initialized at load; invariants preserved per replay) -------------
__device__ float g_qkv   [4 * NTOT];            // atomically accumulated; re-zeroed by qkv_reduce
__device__ float g_q     [B_ * HQ_ * D_];
__device__ float g_knew  [B_ * HKV_ * D_];
__device__ float g_vnew  [B_ * HKV_ * D_];
__device__ float g_scores[B_ * HQ_ * SSTRIDE];
__device__ float g_attn  [B_ * HQ_ * D_];

// ------------- helpers -------------
__device__ __forceinline__ float warpsum(float v) {
    #pragma unroll
    for (int o = 16; o > 0; o >>= 1) v += __shfl_xor_sync(0xFFFFFFFFu, v, o);
    return v;
}
__device__ __forceinline__ float warpmax(float v) {
    #pragma unroll
    for (int o = 16; o > 0; o >>= 1) v = fmaxf(v, __shfl_xor_sync(0xFFFFFFFFu, v, o));
    return v;
}
__device__ __forceinline__ float dot4(float4 a, float4 b) {
    return a.x * b.x + a.y * b.y + a.z * b.z + a.w * b.w;
}
__device__ __forceinline__ float fold(float lo, float hi, int o, int lane) {
    float mine  = (lane & o) ? hi : lo;
    float other = (lane & o) ? lo : hi;
    return mine + __shfl_xor_sync(0xFFFFFFFFu, other, o);
}

// ------------- Kernel 1: QKV GEMV (split-K=64, float4 weights, atomic accumulate) -------------
// grid (12, NSPLIT), block 128. 512 output cols x 64-K chunk, 4 batches.
__global__ void qkv_gemv(const float* __restrict__ h, const float* __restrict__ wq,
                         const float* __restrict__ wk, const float* __restrict__ wv) {
    __shared__ float sh[256];  // [4 batches][64 k]
    int tid = threadIdx.x;
    int k0 = blockIdx.y * 64;
    #pragma unroll
    for (int i = tid; i < 256; i += 128) {    // FIX: strided load (block has 128 threads)
        int b = i >> 6, k = i & 63;
        sh[i] = h[b * HID + k0 + k];
    }
    __syncthreads();
    int c0 = blockIdx.x * 512;
    const float* w; int stride, col;
    if (c0 < 4096)      { w = wq; stride = 4096; col = c0; }
    else if (c0 < 5120) { w = wk; stride = 1024; col = c0 - 4096; }
    else                { w = wv; stride = 1024; col = c0 - 5120; }
    const float* wp = w + (size_t)k0 * stride + col + tid * 4;
    float4 a0 = make_float4(0,0,0,0), a1 = a0, a2 = a0, a3 = a0;
    #pragma unroll 8
    for (int k = 0; k < 64; k++) {
        float4 wv4 = *(const float4*)(wp + (size_t)k * stride);
        float h0 = sh[k], h1 = sh[64 + k], h2 = sh[128 + k], h3 = sh[192 + k];
        a0.x = fmaf(h0, wv4.x, a0.x); a0.y = fmaf(h0, wv4.y, a0.y);
        a0.z = fmaf(h0, wv4.z, a0.z); a0.w = fmaf(h0, wv4.w, a0.w);
        a1.x = fmaf(h1, wv4.x, a1.x); a1.y = fmaf(h1, wv4.y, a1.y);
        a1.z = fmaf(h1, wv4.z, a1.z); a1.w = fmaf(h1, wv4.w, a1.w);
        a2.x = fmaf(h2, wv4.x, a2.x); a2.y = fmaf(h2, wv4.y, a2.y);
        a2.z = fmaf(h2, wv4.z, a2.z); a2.w = fmaf(h2, wv4.w, a2.w);
        a3.x = fmaf(h3, wv4.x, a3.x); a3.y = fmaf(h3, wv4.y, a3.y);
        a3.z = fmaf(h3, wv4.z, a3.z); a3.w = fmaf(h3, wv4.w, a3.w);
    }
    int c = c0 + tid * 4;
    atomicAdd(&g_qkv[c],     a0.x); atomicAdd(&g_qkv[c + 1],     a0.y);
    atomicAdd(&g_qkv[c + 2], a0.z); atomicAdd(&g_qkv[c + 3],     a0.w);
    atomicAdd(&g_qkv[NTOT + c],     a1.x); atomicAdd(&g_qkv[NTOT + c + 1], a1.y);
    atomicAdd(&g_qkv[NTOT + c + 2], a1.z); atomicAdd(&g_qkv[NTOT + c + 3], a1.w);
    atomicAdd(&g_qkv[2*NTOT + c],     a2.x); atomicAdd(&g_qkv[2*NTOT + c + 1], a2.y);
    atomicAdd(&g_qkv[2*NTOT + c + 2], a2.z); atomicAdd(&g_qkv[2*NTOT + c + 3], a2.w);
    atomicAdd(&g_qkv[3*NTOT + c],     a3.x); atomicAdd(&g_qkv[3*NTOT + c + 1], a3.y);
    atomicAdd(&g_qkv[3*NTOT + c + 2], a3.z); atomicAdd(&g_qkv[3*NTOT + c + 3], a3.w);
}

// ------------- Kernel 2: RoPE + accumulator reset -------------
__global__ void qkv_reduce(const float* __restrict__ cosp, const float* __restrict__ sinp) {
    int idx = blockIdx.x * blockDim.x + threadIdx.x;
    if (idx >= 4 * 3584) return;
    int b = idx / 3584, r = idx % 3584;
    float* gq = g_qkv + b * NTOT;
    if (r < 2560) {
        int head = r >> 6, d = r & 63;
        int col1 = head * 128 + d, col2 = col1 + 64;
        float s1 = gq[col1], s2 = gq[col2];
        gq[col1] = 0.f; gq[col2] = 0.f;
        float c1 = cosp[b * D_ + d],      sn1 = sinp[b * D_ + d];
        float c2 = cosp[b * D_ + d + 64], sn2 = sinp[b * D_ + d + 64];
        float r1 = s1 * c1 - s2 * sn1;
        float r2 = s2 * c2 + s1 * sn2;
        if (head < 32) {
            g_q[(b * HQ_ + head) * D_ + d]      = r1;
            g_q[(b * HQ_ + head) * D_ + d + 64] = r2;
        } else {
            int kh = head - 32;
            g_knew[(b * HKV_ + kh) * D_ + d]      = r1;
            g_knew[(b * HKV_ + kh) * D_ + d + 64] = r2;
        }
    } else {
        int lc = r - 2560;
        float s = gq[5120 + lc];
        gq[5120 + lc] = 0.f;
        g_vnew[b * HKV_ * D_ + lc] = s;
    }
}

// ------------- Kernel 3: scores -------------
__global__ void scores_kernel(const float* __restrict__ pk) {
    int bh = blockIdx.y;
    int b = bh >> 3, hkv = bh & 7;
    int tid = threadIdx.x, warp = tid >> 5, lane = tid & 31;
    __shared__ float qsh[512];
    const float* qsrc = g_q + (size_t)(b * HQ_ + hkv * 4) * D_;
    for (int i = tid; i < 512; i += 256) qsh[i] = qsrc[i];
    __syncthreads();
    float4 q0 = *(const float4*)(qsh +   0 + lane * 4);
    float4 q1 = *(const float4*)(qsh + 128 + lane * 4);
    float4 q2 = *(const float4*)(qsh + 256 + lane * 4);
    float4 q3 = *(const float4*)(qsh + 384 + lane * 4);
    int base = blockIdx.x * 256;
    float* srow = g_scores + (size_t)(b * HQ_ + hkv * 4) * SSTRIDE;
    const float* kbase = pk + ((size_t)bh << 20);
    const float* knrow = g_knew + bh * D_;
    int rr = ((lane >> 4) & 1) * 2 + ((lane >> 3) & 1);
    int hh = ((lane >> 2) & 1) * 2 + ((lane >> 1) & 1);
    int p0 = base + warp * 32;
    bool fast = (p0 + 31 < SPAST);
    if (fast) {
        #pragma unroll 2
        for (int j = 0; j < 32; j += 4) {
            int p = p0 + j;
            const float* rp = kbase + ((size_t)p << 7) + lane * 4;
            float4 k0v = *(const float4*)(rp);
            float4 k1v = *(const float4*)(rp + 128);
            float4 k2v = *(const float4*)(rp + 256);
            float4 k3v = *(const float4*)(rp + 384);
            float d00 = dot4(k0v, q0), d01 = dot4(k0v, q1), d02 = dot4(k0v, q2), d03 = dot4(k0v, q3);
            float d10 = dot4(k1v, q0), d11 = dot4(k1v, q1), d12 = dot4(k1v, q2), d13 = dot4(k1v, q3);
            float d20 = dot4(k2v, q0), d21 = dot4(k2v, q1), d22 = dot4(k2v, q2), d23 = dot4(k2v, q3);
            float d30 = dot4(k3v, q0), d31 = dot4(k3v, q1), d32 = dot4(k3v, q2), d33 = dot4(k3v, q3);
            float t00 = fold(d00, d20, 16, lane), t01 = fold(d01, d21, 16, lane);
            float t02 = fold(d02, d22, 16, lane), t03 = fold(d03, d23, 16, lane);
            float t10 = fold(d10, d30, 16, lane), t11 = fold(d11, d31, 16, lane);
            float t12 = fold(d12, d32, 16, lane), t13 = fold(d13, d33, 16, lane);
            float u0 = fold(t00, t10, 8, lane), u1 = fold(t01, t11, 8, lane);
            float u2 = fold(t02, t12, 8, lane), u3 = fold(t03, t13, 8, lane);
            float w0 = fold(u0, u2, 4, lane), w1 = fold(u1, u3, 4, lane);
            float x = fold(w0, w1, 2, lane);
            x += __shfl_xor_sync(0xFFFFFFFFu, x, 1);
            if ((lane & 1) == 0)
                srow[hh * SSTRIDE + p + rr] = x * SCALE;
        }
    } else {
        for (int j = 0; j < 32; j += 4) {
            int p = p0 + j;
            if (p >= KVLEN) break;
            const float* r0p = (p     < SPAST) ? kbase + ((size_t) p      << 7) : knrow;
            const float* r1p = (p + 1 < SPAST) ? kbase + ((size_t)(p + 1) << 7) : knrow;
            const float* r2p = (p + 2 < SPAST) ? kbase + ((size_t)(p + 2) << 7) : knrow;
            const float* r3p = (p + 3 < SPAST) ? kbase + ((size_t)(p + 3) << 7) : knrow;
            float4 k0v = *(const float4*)(r0p + lane * 4);
            float4 k1v = *(const float4*)(r1p + lane * 4);
            float4 k2v = *(const float4*)(r2p + lane * 4);
            float4 k3v = *(const float4*)(r3p + lane * 4);
            float d00 = dot4(k0v, q0), d01 = dot4(k0v, q1), d02 = dot4(k0v, q2), d03 = dot4(k0v, q3);
            float d10 = dot4(k1v, q0), d11 = dot4(k1v, q1), d12 = dot4(k1v, q2), d13 = dot4(k1v, q3);
            float d20 = dot4(k2v, q0), d21 = dot4(k2v, q1), d22 = dot4(k2v, q2), d23 = dot4(k2v, q3);
            float d30 = dot4(k3v, q0), d31 = dot4(k3v, q1), d32 = dot4(k3v, q2), d33 = dot4(k3v, q3);
            float t00 = fold(d00, d20, 16, lane), t01 = fold(d01, d21, 16, lane);
            float t02 = fold(d02, d22, 16, lane), t03 = fold(d03, d23, 16, lane);
            float t10 = fold(d10, d30, 16, lane), t11 = fold(d11, d31, 16, lane);
            float t12 = fold(d12, d32, 16, lane), t13 = fold(d13, d33, 16, lane);
            float u0 = fold(t00, t10, 8, lane), u1 = fold(t01, t11, 8, lane);
            float u2 = fold(t02, t12, 8, lane), u3 = fold(t03, t13, 8, lane);
            float w0 = fold(u0, u2, 4, lane), w1 = fold(u1, u3, 4, lane);
            float x = fold(w0, w1, 2, lane);
            x += __shfl_xor_sync(0xFFFFFFFFu, x, 1);
            if ((lane & 1) == 0 && p + rr < KVLEN)
                srow[hh * SSTRIDE + p + rr] = x * SCALE;
        }
    }
}

// ------------- Kernel 4: FUSED top-256 radix select + softmax + weighted V gather -------------
// One block of 512 threads per (b, hq). Sel list lives in SMEM only.
#define KPT 16
__device__ __forceinline__ void scan_pick256(int* hist, int* warpsums, int* sh_bin,
                                             int* sh_kk, int tid, int nbins) {
    int kk = *sh_kk;
    int v = 0;
    if (tid < nbins) {
        int bin = nbins - 1 - tid;
        v = hist[bin];
        int lane = tid & 31;
        #pragma unroll
        for (int o = 1; o < 32; o <<= 1) {
            int n = __shfl_up_sync(0xFFFFFFFFu, v, o);
            if (lane >= o) v += n;
        }
        if (lane == 31) warpsums[tid >> 5] = v;
    }
    __syncthreads();
    if (tid == 0) {
        int a = 0;
        for (int w = 0; w < (nbins >> 5); w++) { int t = warpsums[w]; warpsums[w] = a; a += t; }
    }
    __syncthreads();
    if (tid < nbins) {
        v += warpsums[tid >> 5];
        int prev = v - hist[nbins - 1 - tid];
        if (v >= kk && prev < kk) { *sh_bin = nbins - 1 - tid; *sh_kk = kk - prev; }
    }
    __syncthreads();
}

__global__ void select_attnv_kernel(const float* __restrict__ pv, float* __restrict__ out) {
    __shared__ int hist[2048];
    __shared__ int warpsums[16];
    __shared__ int sh_bin, sh_kk, sh_wpos, sh_eq;
    __shared__ int selsh[TOKB];
    __shared__ float sc[NKEEP];
    __shared__ int   idxsh[NKEEP];
    __shared__ float red[16];
    __shared__ float M_sh, Z_sh;
    __shared__ float outsh[16 * 128];
    int bh = blockIdx.x, tid = threadIdx.x;
    int b = bh >> 5, hq = bh & 31, hkv = hq >> 2;
    int warp = tid >> 5, lane = tid & 31;
    if (tid < 128) out[bh * 128 + tid] = 0.f;   // zero d_out ahead of out_gemv
    const float* srow = g_scores + (size_t)bh * SSTRIDE;

    // ---- select phase ----
    unsigned key[KPT];
    #pragma unroll
    for (int j = 0; j < 4; j++) hist[tid + j * 512] = 0;
    if (tid == 0) { sh_kk = TOKB; sh_wpos = 0; sh_eq = 0; }
    __syncthreads();
    #pragma unroll
    for (int j = 0; j < KPT; j++) {
        int i = tid + j * 512;
        unsigned u = 0;
        if (i < NCAND) {
            u = __float_as_uint(srow[INITB + i]);
            u = (u & 0x80000000u) ? ~u : (u | 0x80000000u);
            atomicAdd(&hist[u >> 21], 1);
        }
        key[j] = u;
    }
    __syncthreads();
    {   // level-1 scan over 2048 bins, 4 bins/thread (descending)
        int kk = sh_kk;
        int b0 = 2047 - tid * 4;
        int c0 = hist[b0], c1 = hist[b0 - 1], c2 = hist[b0 - 2], c3 = hist[b0 - 3];
        int s = c0 + c1 + c2 + c3;
        int v = s;
        #pragma unroll
        for (int o = 1; o < 32; o <<= 1) {
            int n = __shfl_up_sync(0xFFFFFFFFu, v, o);
            if (lane >= o) v += n;
        }
        if (lane == 31) warpsums[warp] = v;
        __syncthreads();
        if (tid == 0) {
            int a = 0;
            #pragma unroll
            for (int w = 0; w < 16; w++) { int t = warpsums[w]; warpsums[w] = a; a += t; }
        }
        __syncthreads();
        int excl = v - s + warpsums[warp];
        if (excl < kk && excl + s >= kk) {
            int c[4] = {c0, c1, c2, c3};
            int acc = excl;
            #pragma unroll
            for (int q = 0; q < 4; q++) {
                if (acc < kk && acc + c[q] >= kk) { sh_bin = b0 - q; sh_kk = kk - acc; break; }
                acc += c[q];
            }
        }
        __syncthreads();
    }
    unsigned B1 = (unsigned)sh_bin;
    if (tid < 256) hist[tid] = 0;
    __syncthreads();
    #pragma unroll
    for (int j = 0; j < KPT; j++) {
        int i = tid + j * 512;
        if (i < NCAND) {
            unsigned t = key[j] >> 21;
            if (t > B1) selsh[atomicAdd(&sh_wpos, 1)] = INITB + i;
            else if (t == B1) atomicAdd(&hist[(key[j] >> 13) & 255], 1);
        }
    }
    __syncthreads();
    scan_pick256(hist, warpsums, &sh_bin, &sh_kk, tid, 256);
    unsigned P2 = (B1 << 8) | (unsigned)sh_bin;
    if (tid < 256) hist[tid] = 0;
    __syncthreads();
    #pragma unroll
    for (int j = 0; j < KPT; j++) {
        int i = tid + j * 512;
        if (i < NCAND && (key[j] >> 21) == B1) {
            unsigned t = key[j] >> 13;
            if (t > P2) selsh[atomicAdd(&sh_wpos, 1)] = INITB + i;
            else if (t == P2) atomicAdd(&hist[(key[j] >> 5) & 255], 1);
        }
    }
    __syncthreads();
    scan_pick256(hist, warpsums, &sh_bin, &sh_kk, tid, 256);
    unsigned P3 = (P2 << 8) | (unsigned)sh_bin;
    if (tid < 32) hist[tid] = 0;
    __syncthreads();
    #pragma unroll
    for (int j = 0; j < KPT; j++) {
        int i = tid + j * 512;
        if (i < NCAND && (key[j] >> 13) == P2) {
            unsigned t = key[j] >> 5;
            if (t > P3) selsh[atomicAdd(&sh_wpos, 1)] = INITB + i;
            else if (t == P3) atomicAdd(&hist[key[j] & 31], 1);
        }
    }
    __syncthreads();
    scan_pick256(hist, warpsums, &sh_bin, &sh_kk, tid, 32);
    unsigned tau = (P3 << 5) | (unsigned)sh_bin;
    int needeq = sh_kk;
    #pragma unroll
    for (int j = 0; j < KPT; j++) {
        int i = tid + j * 512;
        if (i < NCAND && (key[j] >> 5) == P3) {
            if (key[j] > tau) selsh[atomicAdd(&sh_wpos, 1)] = INITB + i;
            else if (key[j] == tau) {
                if (atomicAdd(&sh_eq, 1) < needeq)
                    selsh[atomicAdd(&sh_wpos, 1)] = INITB + i;
            }
        }
    }
    __syncthreads();

    // ---- attnv phase ----
    for (int i = tid; i < NKEEP; i += 512) {
        int p;
        if (i < INITB) p = i;
        else if (i < INITB + TOKB) p = selsh[i - INITB];
        else p = (KVLEN - RECB) + (i - INITB - TOKB);
        idxsh[i] = p;
        sc[i] = srow[p];
    }
    __syncthreads();
    float m = -INFINITY;
    for (int i = tid; i < NKEEP; i += 512) m = fmaxf(m, sc[i]);
    m = warpmax(m);
    if (lane == 0) red[warp] = m;
    __syncthreads();
    if (tid == 0) {
        float mm = red[0];
        #pragma unroll
        for (int w = 1; w < 16; w++) mm = fmaxf(mm, red[w]);
        M_sh = mm;
    }
    __syncthreads();
    float M = M_sh, z = 0.f;
    for (int i = tid; i < NKEEP; i += 512) {
        float e = __expf(sc[i] - M);
        sc[i] = e;
        z += e;
    }
    z = warpsum(z);
    if (lane == 0) red[warp] = z;
    __syncthreads();
    if (tid == 0) {
        float zz = 0.f;
        #pragma unroll
        for (int w = 0; w < 16; w++) zz += red[w];
        Z_sh = zz;
    }
    __syncthreads();
    float inv = 1.0f / Z_sh;
    float4 acc = make_float4(0.f, 0.f, 0.f, 0.f);
    const float* vbase = pv + ((size_t)(b * HKV_ + hkv) << 20);
    const float* vnrow = g_vnew + (b * HKV_ + hkv) * D_;
    for (int i = warp; i < NKEEP; i += 64) {
        float ww[4];
        const float* vp[4];
        #pragma unroll
        for (int u = 0; u < 4; u++) {
            int ii = i + u * 16;
            bool vld = ii < NKEEP;
            int p = vld ? idxsh[ii] : 0;
            ww[u] = vld ? sc[ii] * inv : 0.f;
            vp[u] = (p < SPAST) ? (vbase + ((size_t)p << 7)) : vnrow;
        }
        float4 v0 = *(const float4*)(vp[0] + lane * 4);
        float4 v1 = *(const float4*)(vp[1] + lane * 4);
        float4 v2 = *(const float4*)(vp[2] + lane * 4);
        float4 v3 = *(const float4*)(vp[3] + lane * 4);
        acc.x = fmaf(ww[0], v0.x, acc.x); acc.y = fmaf(ww[0], v0.y, acc.y);
        acc.z = fmaf(ww[0], v0.z, acc.z); acc.w = fmaf(ww[0], v0.w, acc.w);
        acc.x = fmaf(ww[1], v1.x, acc.x); acc.y = fmaf(ww[1], v1.y, acc.y);
        acc.z = fmaf(ww[1], v1.z, acc.z); acc.w = fmaf(ww[1], v1.w, acc.w);
        acc.x = fmaf(ww[2], v2.x, acc.x); acc.y = fmaf(ww[2], v2.y, acc.y);
        acc.z = fmaf(ww[2], v2.z, acc.z); acc.w = fmaf(ww[2], v2.w, acc.w);
        acc.x = fmaf(ww[3], v3.x, acc.x); acc.y = fmaf(ww[3], v3.y, acc.y);
        acc.z = fmaf(ww[3], v3.z, acc.z); acc.w = fmaf(ww[3], v3.w, acc.w);
    }
    float* os = outsh + warp * 128 + lane * 4;
    os[0] = acc.x; os[1] = acc.y; os[2] = acc.z; os[3] = acc.w;
    __syncthreads();
    if (tid < 128) {
        float s = 0.f;
        #pragma unroll
        for (int w = 0; w < 16; w++) s += outsh[w * 128 + tid];
        g_attn[bh * D_ + tid] = s;
    }
}

// ------------- Kernel 5: output projection GEMV (split-K=64, atomic accumulate) -------------
// grid (8, NSPLIT), block 128.
__global__ void out_gemv(const float* __restrict__ wo, float* __restrict__ out) {
    __shared__ float sh[256];
    int tid = threadIdx.x;
    int k0 = blockIdx.y * 64;
    #pragma unroll
    for (int i = tid; i < 256; i += 128) {    // FIX: strided load (block has 128 threads)
        int b = i >> 6, k = i & 63;
        sh[i] = g_attn[b * HID + k0 + k];
    }
    __syncthreads();
    int col = blockIdx.x * 512 + tid * 4;
    const float* wp = wo + (size_t)k0 * HID + col;
    float4 a0 = make_float4(0,0,0,0), a1 = a0, a2 = a0, a3 = a0;
    #pragma unroll 8
    for (int k = 0; k < 64; k++) {
        float4 wv4 = *(const float4*)(wp + (size_t)k * HID);
        float h0 = sh[k], h1 = sh[64 + k], h2 = sh[128 + k], h3 = sh[192 + k];
        a0.x = fmaf(h0, wv4.x, a0.x); a0.y = fmaf(h0, wv4.y, a0.y);
        a0.z = fmaf(h0, wv4.z, a0.z); a0.w = fmaf(h0, wv4.w, a0.w);
        a1.x = fmaf(h1, wv4.x, a1.x); a1.y = fmaf(h1, wv4.y, a1.y);
        a1.z = fmaf(h1, wv4.z, a1.z); a1.w = fmaf(h1, wv4.w, a1.w);
        a2.x = fmaf(h2, wv4.x, a2.x); a2.y = fmaf(h2, wv4.y, a2.y);
        a2.z = fmaf(h2, wv4.z, a2.z); a2.w = fmaf(h2, wv4.w, a2.w);
        a3.x = fmaf(h3, wv4.x, a3.x); a3.y = fmaf(h3, wv4.y, a3.y);
        a3.z = fmaf(h3, wv4.z, a3.z); a3.w = fmaf(h3, wv4.w, a3.w);
    }
    atomicAdd(&out[col],     a0.x); atomicAdd(&out[col + 1],     a0.y);
    atomicAdd(&out[col + 2], a0.z); atomicAdd(&out[col + 3],     a0.w);
    atomicAdd(&out[HID + col],     a1.x); atomicAdd(&out[HID + col + 1], a1.y);
    atomicAdd(&out[HID + col + 2], a1.z); atomicAdd(&out[HID + col + 3], a1.w);
    atomicAdd(&out[2*HID + col],     a2.x); atomicAdd(&out[2*HID + col + 1], a2.y);
    atomicAdd(&out[2*HID + col + 2], a2.z); atomicAdd(&out[2*HID + col + 3], a2.w);
    atomicAdd(&out[3*HID + col],     a3.x); atomicAdd(&out[3*HID + col + 1], a3.y);
    atomicAdd(&out[3*HID + col + 2], a3.z); atomicAdd(&out[3*HID + col + 3], a3.w);
}

// ------------- launch -------------
extern "C" void kernel_launch(void* const* d_in, const int* in_sizes, int n_in,
                              void* d_out, int out_size) {
    const float* h    = (const float*)d_in[0];
    const float* cosp = (const float*)d_in[1];
    const float* sinp = (const float*)d_in[2];
    const float* pk   = (const float*)d_in[3];
    const float* pv   = (const float*)d_in[4];
    const float* wq   = (const float*)d_in[5];
    const float* wk   = (const float*)d_in[6];
    const float* wv   = (const float*)d_in[7];
    const float* wo   = (const float*)d_in[8];
    float* out = (float*)d_out;

    qkv_gemv<<<dim3(12, NSPLIT), 128>>>(h, wq, wk, wv);
    qkv_reduce<<<(4 * 3584 + 255) / 256, 256>>>(cosp, sinp);
    scores_kernel<<<dim3(33, 32), 256>>>(pk);
    select_attnv_kernel<<<128, 512>>>(pv, out);
    out_gemv<<<dim3(8, NSPLIT), 128>>>(wo, out);
}

// round 7
// speedup vs baseline: 3.6905x; 1.0432x over previous
#include <cuda_runtime.h>
#include <math.h>

// Problem constants
#define B_    4
#define HQ_   32
#define HKV_  8
#define D_    128
#define SPAST 8192
#define KVLEN 8193
#define HID   4096
#define NTOT  6144
#define TOKB  256
#define INITB 4
#define RECB  256
#define NKEEP (INITB + TOKB + RECB)   // 516
#define NCAND 7933                    // positions [4, 7936]
#define SSTRIDE 8208
#define SCALE 0.08838834764831845f
#define NSPLIT 64

// ------------- scratch -------------
__device__ float g_qkv   [4 * NTOT];
__device__ float g_q     [B_ * HQ_ * D_];
__device__ float g_knew  [B_ * HKV_ * D_];
__device__ float g_vnew  [B_ * HKV_ * D_];
__device__ float g_scores[B_ * HQ_ * SSTRIDE];
__device__ float g_attn  [B_ * HQ_ * D_];

// ------------- helpers -------------
__device__ __forceinline__ float warpsum(float v) {
    #pragma unroll
    for (int o = 16; o > 0; o >>= 1) v += __shfl_xor_sync(0xFFFFFFFFu, v, o);
    return v;
}
__device__ __forceinline__ float warpmax(float v) {
    #pragma unroll
    for (int o = 16; o > 0; o >>= 1) v = fmaxf(v, __shfl_xor_sync(0xFFFFFFFFu, v, o));
    return v;
}
__device__ __forceinline__ float dot4(float4 a, float4 b) {
    return a.x * b.x + a.y * b.y + a.z * b.z + a.w * b.w;
}
__device__ __forceinline__ float fold(float lo, float hi, int o, int lane) {
    float mine  = (lane & o) ? hi : lo;
    float other = (lane & o) ? lo : hi;
    return mine + __shfl_xor_sync(0xFFFFFFFFu, other, o);
}
__device__ __forceinline__ unsigned xform(unsigned u) {
    return (u & 0x80000000u) ? ~u : (u | 0x80000000u);
}

// ------------- Kernel 1: QKV GEMV -------------
__global__ void qkv_gemv(const float* __restrict__ h, const float* __restrict__ wq,
                         const float* __restrict__ wk, const float* __restrict__ wv) {
    __shared__ float sh[256];
    int tid = threadIdx.x;
    int k0 = blockIdx.y * 64;
    #pragma unroll
    for (int i = tid; i < 256; i += 128) {
        int b = i >> 6, k = i & 63;
        sh[i] = h[b * HID + k0 + k];
    }
    __syncthreads();
    int c0 = blockIdx.x * 512;
    const float* w; int stride, col;
    if (c0 < 4096)      { w = wq; stride = 4096; col = c0; }
    else if (c0 < 5120) { w = wk; stride = 1024; col = c0 - 4096; }
    else                { w = wv; stride = 1024; col = c0 - 5120; }
    const float* wp = w + (size_t)k0 * stride + col + tid * 4;
    float4 a0 = make_float4(0,0,0,0), a1 = a0, a2 = a0, a3 = a0;
    #pragma unroll 8
    for (int k = 0; k < 64; k++) {
        float4 wv4 = *(const float4*)(wp + (size_t)k * stride);
        float h0 = sh[k], h1 = sh[64 + k], h2 = sh[128 + k], h3 = sh[192 + k];
        a0.x = fmaf(h0, wv4.x, a0.x); a0.y = fmaf(h0, wv4.y, a0.y);
        a0.z = fmaf(h0, wv4.z, a0.z); a0.w = fmaf(h0, wv4.w, a0.w);
        a1.x = fmaf(h1, wv4.x, a1.x); a1.y = fmaf(h1, wv4.y, a1.y);
        a1.z = fmaf(h1, wv4.z, a1.z); a1.w = fmaf(h1, wv4.w, a1.w);
        a2.x = fmaf(h2, wv4.x, a2.x); a2.y = fmaf(h2, wv4.y, a2.y);
        a2.z = fmaf(h2, wv4.z, a2.z); a2.w = fmaf(h2, wv4.w, a2.w);
        a3.x = fmaf(h3, wv4.x, a3.x); a3.y = fmaf(h3, wv4.y, a3.y);
        a3.z = fmaf(h3, wv4.z, a3.z); a3.w = fmaf(h3, wv4.w, a3.w);
    }
    int c = c0 + tid * 4;
    atomicAdd(&g_qkv[c],     a0.x); atomicAdd(&g_qkv[c + 1],     a0.y);
    atomicAdd(&g_qkv[c + 2], a0.z); atomicAdd(&g_qkv[c + 3],     a0.w);
    atomicAdd(&g_qkv[NTOT + c],     a1.x); atomicAdd(&g_qkv[NTOT + c + 1], a1.y);
    atomicAdd(&g_qkv[NTOT + c + 2], a1.z); atomicAdd(&g_qkv[NTOT + c + 3], a1.w);
    atomicAdd(&g_qkv[2*NTOT + c],     a2.x); atomicAdd(&g_qkv[2*NTOT + c + 1], a2.y);
    atomicAdd(&g_qkv[2*NTOT + c + 2], a2.z); atomicAdd(&g_qkv[2*NTOT + c + 3], a2.w);
    atomicAdd(&g_qkv[3*NTOT + c],     a3.x); atomicAdd(&g_qkv[3*NTOT + c + 1], a3.y);
    atomicAdd(&g_qkv[3*NTOT + c + 2], a3.z); atomicAdd(&g_qkv[3*NTOT + c + 3], a3.w);
}

// ------------- Kernel 2: RoPE + accumulator reset -------------
__global__ void qkv_reduce(const float* __restrict__ cosp, const float* __restrict__ sinp) {
    int idx = blockIdx.x * blockDim.x + threadIdx.x;
    if (idx >= 4 * 3584) return;
    int b = idx / 3584, r = idx % 3584;
    float* gq = g_qkv + b * NTOT;
    if (r < 2560) {
        int head = r >> 6, d = r & 63;
        int col1 = head * 128 + d, col2 = col1 + 64;
        float s1 = gq[col1], s2 = gq[col2];
        gq[col1] = 0.f; gq[col2] = 0.f;
        float c1 = cosp[b * D_ + d],      sn1 = sinp[b * D_ + d];
        float c2 = cosp[b * D_ + d + 64], sn2 = sinp[b * D_ + d + 64];
        float r1 = s1 * c1 - s2 * sn1;
        float r2 = s2 * c2 + s1 * sn2;
        if (head < 32) {
            g_q[(b * HQ_ + head) * D_ + d]      = r1;
            g_q[(b * HQ_ + head) * D_ + d + 64] = r2;
        } else {
            int kh = head - 32;
            g_knew[(b * HKV_ + kh) * D_ + d]      = r1;
            g_knew[(b * HKV_ + kh) * D_ + d + 64] = r2;
        }
    } else {
        int lc = r - 2560;
        float s = gq[5120 + lc];
        gq[5120 + lc] = 0.f;
        g_vnew[b * HKV_ * D_ + lc] = s;
    }
}

// ------------- Kernel 3: scores -------------
__global__ void scores_kernel(const float* __restrict__ pk) {
    int bh = blockIdx.y;
    int b = bh >> 3, hkv = bh & 7;
    int tid = threadIdx.x, warp = tid >> 5, lane = tid & 31;
    __shared__ float qsh[512];
    const float* qsrc = g_q + (size_t)(b * HQ_ + hkv * 4) * D_;
    for (int i = tid; i < 512; i += 256) qsh[i] = qsrc[i];
    __syncthreads();
    float4 q0 = *(const float4*)(qsh +   0 + lane * 4);
    float4 q1 = *(const float4*)(qsh + 128 + lane * 4);
    float4 q2 = *(const float4*)(qsh + 256 + lane * 4);
    float4 q3 = *(const float4*)(qsh + 384 + lane * 4);
    int base = blockIdx.x * 256;
    float* srow = g_scores + (size_t)(b * HQ_ + hkv * 4) * SSTRIDE;
    const float* kbase = pk + ((size_t)bh << 20);
    const float* knrow = g_knew + bh * D_;
    int rr = ((lane >> 4) & 1) * 2 + ((lane >> 3) & 1);
    int hh = ((lane >> 2) & 1) * 2 + ((lane >> 1) & 1);
    int p0 = base + warp * 32;
    bool fast = (p0 + 31 < SPAST);
    if (fast) {
        #pragma unroll 2
        for (int j = 0; j < 32; j += 4) {
            int p = p0 + j;
            const float* rp = kbase + ((size_t)p << 7) + lane * 4;
            float4 k0v = *(const float4*)(rp);
            float4 k1v = *(const float4*)(rp + 128);
            float4 k2v = *(const float4*)(rp + 256);
            float4 k3v = *(const float4*)(rp + 384);
            float d00 = dot4(k0v, q0), d01 = dot4(k0v, q1), d02 = dot4(k0v, q2), d03 = dot4(k0v, q3);
            float d10 = dot4(k1v, q0), d11 = dot4(k1v, q1), d12 = dot4(k1v, q2), d13 = dot4(k1v, q3);
            float d20 = dot4(k2v, q0), d21 = dot4(k2v, q1), d22 = dot4(k2v, q2), d23 = dot4(k2v, q3);
            float d30 = dot4(k3v, q0), d31 = dot4(k3v, q1), d32 = dot4(k3v, q2), d33 = dot4(k3v, q3);
            float t00 = fold(d00, d20, 16, lane), t01 = fold(d01, d21, 16, lane);
            float t02 = fold(d02, d22, 16, lane), t03 = fold(d03, d23, 16, lane);
            float t10 = fold(d10, d30, 16, lane), t11 = fold(d11, d31, 16, lane);
            float t12 = fold(d12, d32, 16, lane), t13 = fold(d13, d33, 16, lane);
            float u0 = fold(t00, t10, 8, lane), u1 = fold(t01, t11, 8, lane);
            float u2 = fold(t02, t12, 8, lane), u3 = fold(t03, t13, 8, lane);
            float w0 = fold(u0, u2, 4, lane), w1 = fold(u1, u3, 4, lane);
            float x = fold(w0, w1, 2, lane);
            x += __shfl_xor_sync(0xFFFFFFFFu, x, 1);
            if ((lane & 1) == 0)
                srow[hh * SSTRIDE + p + rr] = x * SCALE;
        }
    } else {
        for (int j = 0; j < 32; j += 4) {
            int p = p0 + j;
            if (p >= KVLEN) break;
            const float* r0p = (p     < SPAST) ? kbase + ((size_t) p      << 7) : knrow;
            const float* r1p = (p + 1 < SPAST) ? kbase + ((size_t)(p + 1) << 7) : knrow;
            const float* r2p = (p + 2 < SPAST) ? kbase + ((size_t)(p + 2) << 7) : knrow;
            const float* r3p = (p + 3 < SPAST) ? kbase + ((size_t)(p + 3) << 7) : knrow;
            float4 k0v = *(const float4*)(r0p + lane * 4);
            float4 k1v = *(const float4*)(r1p + lane * 4);
            float4 k2v = *(const float4*)(r2p + lane * 4);
            float4 k3v = *(const float4*)(r3p + lane * 4);
            float d00 = dot4(k0v, q0), d01 = dot4(k0v, q1), d02 = dot4(k0v, q2), d03 = dot4(k0v, q3);
            float d10 = dot4(k1v, q0), d11 = dot4(k1v, q1), d12 = dot4(k1v, q2), d13 = dot4(k1v, q3);
            float d20 = dot4(k2v, q0), d21 = dot4(k2v, q1), d22 = dot4(k2v, q2), d23 = dot4(k2v, q3);
            float d30 = dot4(k3v, q0), d31 = dot4(k3v, q1), d32 = dot4(k3v, q2), d33 = dot4(k3v, q3);
            float t00 = fold(d00, d20, 16, lane), t01 = fold(d01, d21, 16, lane);
            float t02 = fold(d02, d22, 16, lane), t03 = fold(d03, d23, 16, lane);
            float t10 = fold(d10, d30, 16, lane), t11 = fold(d11, d31, 16, lane);
            float t12 = fold(d12, d32, 16, lane), t13 = fold(d13, d33, 16, lane);
            float u0 = fold(t00, t10, 8, lane), u1 = fold(t01, t11, 8, lane);
            float u2 = fold(t02, t12, 8, lane), u3 = fold(t03, t13, 8, lane);
            float w0 = fold(u0, u2, 4, lane), w1 = fold(u1, u3, 4, lane);
            float x = fold(w0, w1, 2, lane);
            x += __shfl_xor_sync(0xFFFFFFFFu, x, 1);
            if ((lane & 1) == 0 && p + rr < KVLEN)
                srow[hh * SSTRIDE + p + rr] = x * SCALE;
        }
    }
}

// ------------- Kernel 4: FUSED select (3-level radix) + softmax + V gather -------------
// 1024 threads per block, one block per (b, hq). 8 keys/thread in registers.
#define KPT 8
// descending block scan over hist of (1024*NB) bins; picks threshold bin.
template<int NB>
__device__ __forceinline__ void scan_pick_desc(const int* hist, int* warpsums,
                                               int* sh_bin, int* sh_kk, int tid) {
    int kk = *sh_kk;
    int nb = 1024 * NB;
    int b0 = nb - 1 - tid * NB;
    int c[NB]; int s = 0;
    #pragma unroll
    for (int q = 0; q < NB; q++) { c[q] = hist[b0 - q]; s += c[q]; }
    int v = s; int lane = tid & 31;
    #pragma unroll
    for (int o = 1; o < 32; o <<= 1) {
        int n = __shfl_up_sync(0xFFFFFFFFu, v, o);
        if (lane >= o) v += n;
    }
    if (lane == 31) warpsums[tid >> 5] = v;
    __syncthreads();
    if (tid == 0) {
        int a = 0;
        #pragma unroll
        for (int w = 0; w < 32; w++) { int t = warpsums[w]; warpsums[w] = a; a += t; }
    }
    __syncthreads();
    int excl = v - s + warpsums[tid >> 5];
    if (excl < kk && excl + s >= kk) {
        int acc = excl;
        #pragma unroll
        for (int q = 0; q < NB; q++) {
            if (acc < kk && acc + c[q] >= kk) { *sh_bin = b0 - q; *sh_kk = kk - acc; break; }
            acc += c[q];
        }
    }
    __syncthreads();
}
// 256-bin descending pick (tid<256 active)
__device__ __forceinline__ void scan_pick_256(const int* hist, int* warpsums,
                                              int* sh_bin, int* sh_kk, int tid) {
    int kk = *sh_kk;
    int v = 0, s = 0;
    if (tid < 256) {
        s = hist[255 - tid];
        v = s;
        int lane = tid & 31;
        #pragma unroll
        for (int o = 1; o < 32; o <<= 1) {
            int n = __shfl_up_sync(0xFFFFFFFFu, v, o);
            if (lane >= o) v += n;
        }
        if (lane == 31) warpsums[tid >> 5] = v;
    }
    __syncthreads();
    if (tid == 0) {
        int a = 0;
        #pragma unroll
        for (int w = 0; w < 8; w++) { int t = warpsums[w]; warpsums[w] = a; a += t; }
    }
    __syncthreads();
    if (tid < 256) {
        v += warpsums[tid >> 5];
        int prev = v - s;
        if (v >= kk && prev < kk) { *sh_bin = 255 - tid; *sh_kk = kk - prev; }
    }
    __syncthreads();
}

__global__ __launch_bounds__(1024, 1)
void select_attnv_kernel(const float* __restrict__ pv, float* __restrict__ out) {
    __shared__ __align__(16) char s_buf[32768];     // hist (<=8192 ints) / outsh alias
    __shared__ int warpsums[32];
    __shared__ int sh_bin, sh_kk, sh_wpos, sh_eq;
    __shared__ int selsh[TOKB];
    __shared__ float sc[NKEEP];
    __shared__ int   idxsh[NKEEP];
    __shared__ float red[32];
    __shared__ float M_sh, Z_sh;
    int* hist = (int*)s_buf;
    float* outsh = (float*)s_buf;                   // alive only after radix done

    int bh = blockIdx.x, tid = threadIdx.x;
    int b = bh >> 5, hq = bh & 31, hkv = hq >> 2;
    int warp = tid >> 5, lane = tid & 31;
    if (tid < 128) out[bh * 128 + tid] = 0.f;
    const float* srow = g_scores + (size_t)bh * SSTRIDE;

    // ---- load keys (contiguous 8/thread, float4) + level-1 hist (2048 bins) ----
    hist[tid] = 0; hist[tid + 1024] = 0;
    if (tid == 0) { sh_kk = TOKB; sh_wpos = 0; sh_eq = 0; }
    __syncthreads();
    unsigned key[KPT];
    int ibase = tid * KPT;
    if (ibase + KPT - 1 < NCAND) {
        float4 f0 = *(const float4*)(srow + INITB + ibase);
        float4 f1 = *(const float4*)(srow + INITB + ibase + 4);
        key[0] = xform(__float_as_uint(f0.x)); key[1] = xform(__float_as_uint(f0.y));
        key[2] = xform(__float_as_uint(f0.z)); key[3] = xform(__float_as_uint(f0.w));
        key[4] = xform(__float_as_uint(f1.x)); key[5] = xform(__float_as_uint(f1.y));
        key[6] = xform(__float_as_uint(f1.z)); key[7] = xform(__float_as_uint(f1.w));
        #pragma unroll
        for (int j = 0; j < KPT; j++) atomicAdd(&hist[key[j] >> 21], 1);
    } else {
        #pragma unroll
        for (int j = 0; j < KPT; j++) {
            int i = ibase + j;
            unsigned u = 0;
            if (i < NCAND) {
                u = xform(__float_as_uint(srow[INITB + i]));
                atomicAdd(&hist[u >> 21], 1);
            }
            key[j] = u;
        }
    }
    __syncthreads();
    scan_pick_desc<2>(hist, warpsums, &sh_bin, &sh_kk, tid);
    unsigned B1 = (unsigned)sh_bin;
    // clear 8192-bin hist for level 2
    #pragma unroll
    for (int q = 0; q < 8; q++) hist[tid + q * 1024] = 0;
    __syncthreads();
    // classify-1: winners out; ties build level-2 hist over bits[20:8]
    #pragma unroll
    for (int j = 0; j < KPT; j++) {
        int i = ibase + j;
        if (i < NCAND) {
            unsigned t = key[j] >> 21;
            if (t > B1) selsh[atomicAdd(&sh_wpos, 1)] = INITB + i;
            else if (t == B1) atomicAdd(&hist[(key[j] >> 8) & 0x1FFF], 1);
        }
    }
    __syncthreads();
    scan_pick_desc<8>(hist, warpsums, &sh_bin, &sh_kk, tid);
    unsigned B2 = (unsigned)sh_bin;
    unsigned P24 = (B1 << 13) | B2;     // resolved top 24 bits
    if (tid < 256) hist[tid] = 0;
    __syncthreads();
    // classify-2: winners out; ties build level-3 hist over low 8 bits
    #pragma unroll
    for (int j = 0; j < KPT; j++) {
        int i = ibase + j;
        if (i < NCAND && (key[j] >> 21) == B1) {
            unsigned t = (key[j] >> 8) & 0x1FFF;
            if (t > B2) selsh[atomicAdd(&sh_wpos, 1)] = INITB + i;
            else if (t == B2) atomicAdd(&hist[key[j] & 255], 1);
        }
    }
    __syncthreads();
    scan_pick_256(hist, warpsums, &sh_bin, &sh_kk, tid);
    unsigned tau = (P24 << 8) | (unsigned)sh_bin;
    int needeq = sh_kk;
    // final: winners above tau + exact tie claim
    #pragma unroll
    for (int j = 0; j < KPT; j++) {
        int i = ibase + j;
        if (i < NCAND && (key[j] >> 8) == P24) {
            if (key[j] > tau) selsh[atomicAdd(&sh_wpos, 1)] = INITB + i;
            else if (key[j] == tau) {
                if (atomicAdd(&sh_eq, 1) < needeq)
                    selsh[atomicAdd(&sh_wpos, 1)] = INITB + i;
            }
        }
    }
    __syncthreads();

    // ---- attnv phase ----
    if (tid < NKEEP) {
        int i = tid, p;
        if (i < INITB) p = i;
        else if (i < INITB + TOKB) p = selsh[i - INITB];
        else p = (KVLEN - RECB) + (i - INITB - TOKB);
        idxsh[i] = p;
        sc[i] = srow[p];
    }
    __syncthreads();
    float m = (tid < NKEEP) ? sc[tid] : -INFINITY;
    m = warpmax(m);
    if (lane == 0) red[warp] = m;
    __syncthreads();
    if (tid == 0) {
        float mm = red[0];
        #pragma unroll
        for (int w = 1; w < 32; w++) mm = fmaxf(mm, red[w]);
        M_sh = mm;
    }
    __syncthreads();
    float M = M_sh;
    float z = 0.f;
    if (tid < NKEEP) {
        float e = __expf(sc[tid] - M);
        sc[tid] = e;
        z = e;
    }
    z = warpsum(z);
    if (lane == 0) red[warp] = z;
    __syncthreads();
    if (tid == 0) {
        float zz = 0.f;
        #pragma unroll
        for (int w = 0; w < 32; w++) zz += red[w];
        Z_sh = zz;
    }
    __syncthreads();
    float inv = 1.0f / Z_sh;
    float4 acc = make_float4(0.f, 0.f, 0.f, 0.f);
    const float* vbase = pv + ((size_t)(b * HKV_ + hkv) << 20);
    const float* vnrow = g_vnew + (b * HKV_ + hkv) * D_;
    for (int i = warp; i < NKEEP; i += 128) {
        float ww[4];
        const float* vp[4];
        #pragma unroll
        for (int u = 0; u < 4; u++) {
            int ii = i + u * 32;
            bool vld = ii < NKEEP;
            int p = vld ? idxsh[ii] : 0;
            ww[u] = vld ? sc[ii] * inv : 0.f;
            vp[u] = (p < SPAST) ? (vbase + ((size_t)p << 7)) : vnrow;
        }
        float4 v0 = *(const float4*)(vp[0] + lane * 4);
        float4 v1 = *(const float4*)(vp[1] + lane * 4);
        float4 v2 = *(const float4*)(vp[2] + lane * 4);
        float4 v3 = *(const float4*)(vp[3] + lane * 4);
        acc.x = fmaf(ww[0], v0.x, acc.x); acc.y = fmaf(ww[0], v0.y, acc.y);
        acc.z = fmaf(ww[0], v0.z, acc.z); acc.w = fmaf(ww[0], v0.w, acc.w);
        acc.x = fmaf(ww[1], v1.x, acc.x); acc.y = fmaf(ww[1], v1.y, acc.y);
        acc.z = fmaf(ww[1], v1.z, acc.z); acc.w = fmaf(ww[1], v1.w, acc.w);
        acc.x = fmaf(ww[2], v2.x, acc.x); acc.y = fmaf(ww[2], v2.y, acc.y);
        acc.z = fmaf(ww[2], v2.z, acc.z); acc.w = fmaf(ww[2], v2.w, acc.w);
        acc.x = fmaf(ww[3], v3.x, acc.x); acc.y = fmaf(ww[3], v3.y, acc.y);
        acc.z = fmaf(ww[3], v3.z, acc.z); acc.w = fmaf(ww[3], v3.w, acc.w);
    }
    // hist/s_buf is dead; reuse as outsh
    float* os = outsh + warp * 128 + lane * 4;
    os[0] = acc.x; os[1] = acc.y; os[2] = acc.z; os[3] = acc.w;
    __syncthreads();
    if (tid < 128) {
        float s = 0.f;
        #pragma unroll
        for (int w = 0; w < 32; w++) s += outsh[w * 128 + tid];
        g_attn[bh * D_ + tid] = s;
    }
}

// ------------- Kernel 5: output projection GEMV -------------
__global__ void out_gemv(const float* __restrict__ wo, float* __restrict__ out) {
    __shared__ float sh[256];
    int tid = threadIdx.x;
    int k0 = blockIdx.y * 64;
    #pragma unroll
    for (int i = tid; i < 256; i += 128) {
        int b = i >> 6, k = i & 63;
        sh[i] = g_attn[b * HID + k0 + k];
    }
    __syncthreads();
    int col = blockIdx.x * 512 + tid * 4;
    const float* wp = wo + (size_t)k0 * HID + col;
    float4 a0 = make_float4(0,0,0,0), a1 = a0, a2 = a0, a3 = a0;
    #pragma unroll 8
    for (int k = 0; k < 64; k++) {
        float4 wv4 = *(const float4*)(wp + (size_t)k * HID);
        float h0 = sh[k], h1 = sh[64 + k], h2 = sh[128 + k], h3 = sh[192 + k];
        a0.x = fmaf(h0, wv4.x, a0.x); a0.y = fmaf(h0, wv4.y, a0.y);
        a0.z = fmaf(h0, wv4.z, a0.z); a0.w = fmaf(h0, wv4.w, a0.w);
        a1.x = fmaf(h1, wv4.x, a1.x); a1.y = fmaf(h1, wv4.y, a1.y);
        a1.z = fmaf(h1, wv4.z, a1.z); a1.w = fmaf(h1, wv4.w, a1.w);
        a2.x = fmaf(h2, wv4.x, a2.x); a2.y = fmaf(h2, wv4.y, a2.y);
        a2.z = fmaf(h2, wv4.z, a2.z); a2.w = fmaf(h2, wv4.w, a2.w);
        a3.x = fmaf(h3, wv4.x, a3.x); a3.y = fmaf(h3, wv4.y, a3.y);
        a3.z = fmaf(h3, wv4.z, a3.z); a3.w = fmaf(h3, wv4.w, a3.w);
    }
    atomicAdd(&out[col],     a0.x); atomicAdd(&out[col + 1],     a0.y);
    atomicAdd(&out[col + 2], a0.z); atomicAdd(&out[col + 3],     a0.w);
    atomicAdd(&out[HID + col],     a1.x); atomicAdd(&out[HID + col + 1], a1.y);
    atomicAdd(&out[HID + col + 2], a1.z); atomicAdd(&out[HID + col + 3], a1.w);
    atomicAdd(&out[2*HID + col],     a2.x); atomicAdd(&out[2*HID + col + 1], a2.y);
    atomicAdd(&out[2*HID + col + 2], a2.z); atomicAdd(&out[2*HID + col + 3], a2.w);
    atomicAdd(&out[3*HID + col],     a3.x); atomicAdd(&out[3*HID + col + 1], a3.y);
    atomicAdd(&out[3*HID + col + 2], a3.z); atomicAdd(&out[3*HID + col + 3], a3.w);
}

// ------------- launch -------------
extern "C" void kernel_launch(void* const* d_in, const int* in_sizes, int n_in,
                              void* d_out, int out_size) {
    const float* h    = (const float*)d_in[0];
    const float* cosp = (const float*)d_in[1];
    const float* sinp = (const float*)d_in[2];
    const float* pk   = (const float*)d_in[3];
    const float* pv   = (const float*)d_in[4];
    const float* wq   = (const float*)d_in[5];
    const float* wk   = (const float*)d_in[6];
    const float* wv   = (const float*)d_in[7];
    const float* wo   = (const float*)d_in[8];
    float* out = (float*)d_out;

    qkv_gemv<<<dim3(12, NSPLIT), 128>>>(h, wq, wk, wv);
    qkv_reduce<<<(4 * 3584 + 255) / 256, 256>>>(cosp, sinp);
    scores_kernel<<<dim3(33, 32), 256>>>(pk);
    select_attnv_kernel<<<128, 1024>>>(pv, out);
    out_gemv<<<dim3(8, NSPLIT), 128>>>(wo, out);
}